// round 5
// baseline (speedup 1.0000x reference)
#include <cuda_runtime.h>
#include <cuda_bf16.h>

// Problem constants (fixed shapes from reference)
#define BB 2
#define CC 512
#define LL 1024            // D*H*W = 8*8*16
#define DI 1024            // D_INNER
#define NS 16              // D_STATE
#define DTR 32             // DT_RANK
#define NTOK (BB*LL)       // 2048 tokens

// ---------------- scratch (device globals: no allocation allowed) ----------------
__device__ float g_xn[NTOK * CC];        // 4 MB   layernorm output
__device__ float g_xz[NTOK * 2 * DI];    // 16 MB  in-proj output (xi | z)
__device__ float g_xc[NTOK * DI];        // 8 MB   conv+silu output
__device__ float g_proj[NTOK * 64];      // 0.5 MB x-proj output (dtr|B|C)
__device__ float g_dt[NTOK * DI];        // 8 MB   softplus(dt)
__device__ float g_y[NTOK * DI];         // 8 MB   scan output * silu(z)

// ---------------- LayerNorm: one block per token ----------------
__global__ __launch_bounds__(256) void ln_kernel(const float* __restrict__ x,
                          const float* __restrict__ gamma,
                          const float* __restrict__ beta,
                          float* __restrict__ xn)
{
    int t = blockIdx.x;            // token
    int b = t >> 10, l = t & (LL - 1);
    int tid = threadIdx.x;         // 256 threads, 2 channels each
    const float* xb = x + (size_t)b * CC * LL + l;
    float v0 = xb[(size_t)tid * LL];
    float v1 = xb[(size_t)(tid + 256) * LL];
    float s = v0 + v1, q = v0 * v0 + v1 * v1;
    #pragma unroll
    for (int off = 16; off; off >>= 1) {
        s += __shfl_xor_sync(0xffffffffu, s, off);
        q += __shfl_xor_sync(0xffffffffu, q, off);
    }
    __shared__ float sh_s[8], sh_q[8];
    if ((tid & 31) == 0) { sh_s[tid >> 5] = s; sh_q[tid >> 5] = q; }
    __syncthreads();
    float ts = 0.f, tq = 0.f;
    #pragma unroll
    for (int i = 0; i < 8; i++) { ts += sh_s[i]; tq += sh_q[i]; }
    float mu = ts * (1.f / CC);
    float var = tq * (1.f / CC) - mu * mu;
    float rs = rsqrtf(var + 1e-5f);
    xn[t * CC + tid]       = (v0 - mu) * rs * gamma[tid]       + beta[tid];
    xn[t * CC + tid + 256] = (v1 - mu) * rs * gamma[tid + 256] + beta[tid + 256];
}

// ---------------- generic tiled SGEMM with fused epilogues ----------------
// EP=0: plain store Co[m*N+n]
// EP=1: softplus(acc + ep[n])            (dt projection)
// EP=2: transposed residual write: Co[b*CC*LL + n*LL + l] = acc + ep[same]
template<int BM, int BN, int BK, int TM, int TN, int EP>
__global__ __launch_bounds__(256) void sgemm_kernel(const float* __restrict__ A, int lda,
                             const float* __restrict__ B, int ldb,
                             float* __restrict__ Co,
                             const float* __restrict__ ep,
                             int M, int N, int K)
{
    __shared__ float As[BK][BM];
    __shared__ float Bs[BK][BN];
    const int tid = threadIdx.x;                 // 256 threads
    const int m0 = blockIdx.y * BM;
    const int n0 = blockIdx.x * BN;
    const int tcols = BN / TN;
    const int tr = tid / tcols, tc = tid % tcols;

    float acc[TM][TN];
    #pragma unroll
    for (int i = 0; i < TM; i++)
        #pragma unroll
        for (int j = 0; j < TN; j++) acc[i][j] = 0.f;

    for (int k0 = 0; k0 < K; k0 += BK) {
        // load A tile (store transposed into As[k][m])
        for (int i = tid * 4; i < BM * BK; i += 256 * 4) {
            int r = i / BK, c = i % BK;
            float4 v = *reinterpret_cast<const float4*>(&A[(size_t)(m0 + r) * lda + k0 + c]);
            As[c + 0][r] = v.x; As[c + 1][r] = v.y;
            As[c + 2][r] = v.z; As[c + 3][r] = v.w;
        }
        // load B tile
        for (int i = tid * 4; i < BK * BN; i += 256 * 4) {
            int r = i / BN, c = i % BN;
            *reinterpret_cast<float4*>(&Bs[r][c]) =
                *reinterpret_cast<const float4*>(&B[(size_t)(k0 + r) * ldb + n0 + c]);
        }
        __syncthreads();
        #pragma unroll
        for (int kk = 0; kk < BK; ++kk) {
            float ra[TM], rb[TN];
            #pragma unroll
            for (int i = 0; i < TM; i += 4) {
                float4 v = *reinterpret_cast<const float4*>(&As[kk][tr * TM + i]);
                ra[i] = v.x; ra[i + 1] = v.y; ra[i + 2] = v.z; ra[i + 3] = v.w;
            }
            #pragma unroll
            for (int j = 0; j < TN; j += 4) {
                float4 v = *reinterpret_cast<const float4*>(&Bs[kk][tc * TN + j]);
                rb[j] = v.x; rb[j + 1] = v.y; rb[j + 2] = v.z; rb[j + 3] = v.w;
            }
            #pragma unroll
            for (int i = 0; i < TM; i++)
                #pragma unroll
                for (int j = 0; j < TN; j++)
                    acc[i][j] = fmaf(ra[i], rb[j], acc[i][j]);
        }
        __syncthreads();
    }

    #pragma unroll
    for (int i = 0; i < TM; i++) {
        int m = m0 + tr * TM + i;
        #pragma unroll
        for (int j = 0; j < TN; j++) {
            int n = n0 + tc * TN + j;
            float v = acc[i][j];
            if (EP == 0) {
                Co[(size_t)m * N + n] = v;
            } else if (EP == 1) {
                v += ep[n];
                Co[(size_t)m * N + n] = (v > 20.f) ? v : log1pf(__expf(v));
            } else {
                int b = m >> 10, l = m & (LL - 1);
                size_t idx = ((size_t)b * CC + n) * LL + l;
                Co[idx] = v + ep[idx];
            }
        }
    }
}

// small-M variant (TM=2, scalar A-fragment loads)
template<int BM, int BN, int BK, int TN, int EP>
__global__ __launch_bounds__(256) void sgemm_small_kernel(const float* __restrict__ A, int lda,
                                   const float* __restrict__ B, int ldb,
                                   float* __restrict__ Co,
                                   const float* __restrict__ ep,
                                   int M, int N, int K)
{
    const int TM = 2;
    __shared__ float As[BK][BM];
    __shared__ float Bs[BK][BN];
    const int tid = threadIdx.x;
    const int m0 = blockIdx.y * BM;
    const int n0 = blockIdx.x * BN;
    const int tcols = BN / TN;
    const int tr = tid / tcols, tc = tid % tcols;

    float acc[TM][TN];
    #pragma unroll
    for (int i = 0; i < TM; i++)
        #pragma unroll
        for (int j = 0; j < TN; j++) acc[i][j] = 0.f;

    for (int k0 = 0; k0 < K; k0 += BK) {
        for (int i = tid * 4; i < BM * BK; i += 256 * 4) {
            int r = i / BK, c = i % BK;
            float4 v = *reinterpret_cast<const float4*>(&A[(size_t)(m0 + r) * lda + k0 + c]);
            As[c + 0][r] = v.x; As[c + 1][r] = v.y;
            As[c + 2][r] = v.z; As[c + 3][r] = v.w;
        }
        for (int i = tid * 4; i < BK * BN; i += 256 * 4) {
            int r = i / BN, c = i % BN;
            *reinterpret_cast<float4*>(&Bs[r][c]) =
                *reinterpret_cast<const float4*>(&B[(size_t)(k0 + r) * ldb + n0 + c]);
        }
        __syncthreads();
        #pragma unroll
        for (int kk = 0; kk < BK; ++kk) {
            float ra[TM], rb[TN];
            #pragma unroll
            for (int i = 0; i < TM; i++) ra[i] = As[kk][tr * TM + i];
            #pragma unroll
            for (int j = 0; j < TN; j += 4) {
                float4 v = *reinterpret_cast<const float4*>(&Bs[kk][tc * TN + j]);
                rb[j] = v.x; rb[j + 1] = v.y; rb[j + 2] = v.z; rb[j + 3] = v.w;
            }
            #pragma unroll
            for (int i = 0; i < TM; i++)
                #pragma unroll
                for (int j = 0; j < TN; j++)
                    acc[i][j] = fmaf(ra[i], rb[j], acc[i][j]);
        }
        __syncthreads();
    }
    #pragma unroll
    for (int i = 0; i < TM; i++) {
        int m = m0 + tr * TM + i;
        #pragma unroll
        for (int j = 0; j < TN; j++) {
            int n = n0 + tc * TN + j;
            Co[(size_t)m * N + n] = acc[i][j];
        }
    }
}

// ---------------- causal depthwise conv (k=4) + SiLU ----------------
__global__ __launch_bounds__(256) void conv_silu_kernel(const float* __restrict__ xz,
                                 const float* __restrict__ conv_w,
                                 const float* __restrict__ conv_b,
                                 float* __restrict__ xc)
{
    int idx = blockIdx.x * 256 + threadIdx.x;   // over NTOK*DI
    int d = idx & (DI - 1);
    int t = idx >> 10;
    int l = t & (LL - 1);
    float v = conv_b[d];
    const float* w = &conv_w[d * 4];
    #pragma unroll
    for (int k = 0; k < 4; ++k) {
        int ll = l - 3 + k;
        if (ll >= 0) v = fmaf(w[k], xz[(size_t)(t - 3 + k) * (2 * DI) + d], v);
    }
    float sg = 1.f / (1.f + __expf(-v));
    xc[idx] = v * sg;
}

// ---------------- selective scan: 16 lanes per (b,d) sequence ----------------
__global__ __launch_bounds__(256) void scan_kernel(const float* __restrict__ dt,
                            const float* __restrict__ xc,
                            const float* __restrict__ proj,
                            const float* __restrict__ xz,
                            const float* __restrict__ A_log,
                            const float* __restrict__ D_param,
                            float* __restrict__ y)
{
    int tid = threadIdx.x;
    int n = tid & 15;                       // state index
    int g = blockIdx.x * 16 + (tid >> 4);   // group = b*DI + d
    int b = g >> 10, d = g & (DI - 1);
    float a = -__expf(A_log[d * NS + n]);
    float Dp = D_param[d];
    float h = 0.f;
    int tbase = b * LL;
    for (int l = 0; l < LL; ++l) {
        int t = tbase + l;
        float dtv = dt[(size_t)t * DI + d];
        float xcv = xc[(size_t)t * DI + d];
        float Bv  = proj[t * 64 + DTR + n];
        float Cv  = proj[t * 64 + DTR + NS + n];
        float dA  = __expf(dtv * a);
        h = fmaf(dA, h, dtv * xcv * Bv);
        float p = h * Cv;
        p += __shfl_xor_sync(0xffffffffu, p, 8);
        p += __shfl_xor_sync(0xffffffffu, p, 4);
        p += __shfl_xor_sync(0xffffffffu, p, 2);
        p += __shfl_xor_sync(0xffffffffu, p, 1);
        if (n == 0) {
            float zv = xz[(size_t)t * (2 * DI) + DI + d];
            float sg = 1.f / (1.f + __expf(-zv));
            y[(size_t)t * DI + d] = (p + Dp * xcv) * (zv * sg);
        }
    }
}

// ---------------- launch ----------------
extern "C" void kernel_launch(void* const* d_in, const int* in_sizes, int n_in,
                              void* d_out, int out_size)
{
    const float* x       = (const float*)d_in[0];
    const float* gamma   = (const float*)d_in[1];
    const float* beta    = (const float*)d_in[2];
    const float* W_in    = (const float*)d_in[3];
    const float* conv_w  = (const float*)d_in[4];
    const float* conv_b  = (const float*)d_in[5];
    const float* W_x     = (const float*)d_in[6];
    const float* W_dt    = (const float*)d_in[7];
    const float* b_dt    = (const float*)d_in[8];
    const float* A_log   = (const float*)d_in[9];
    const float* D_param = (const float*)d_in[10];
    const float* W_out   = (const float*)d_in[11];
    float* out = (float*)d_out;

    float *p_xn, *p_xz, *p_xc, *p_proj, *p_dt, *p_y;
    cudaGetSymbolAddress((void**)&p_xn,   g_xn);
    cudaGetSymbolAddress((void**)&p_xz,   g_xz);
    cudaGetSymbolAddress((void**)&p_xc,   g_xc);
    cudaGetSymbolAddress((void**)&p_proj, g_proj);
    cudaGetSymbolAddress((void**)&p_dt,   g_dt);
    cudaGetSymbolAddress((void**)&p_y,    g_y);

    // 1) LayerNorm
    ln_kernel<<<NTOK, 256>>>(x, gamma, beta, p_xn);

    // 2) in-proj GEMM: (2048x512) @ (512x2048)
    {
        dim3 grid(2 * DI / 128, NTOK / 128);
        sgemm_kernel<128, 128, 8, 8, 8, 0><<<grid, 256>>>(
            p_xn, CC, W_in, 2 * DI, p_xz, nullptr, NTOK, 2 * DI, CC);
    }

    // 3) causal conv + SiLU
    conv_silu_kernel<<<NTOK * DI / 256, 256>>>(p_xz, conv_w, conv_b, p_xc);

    // 4) x-proj GEMM: (2048x1024) @ (1024x64)
    {
        dim3 grid(1, NTOK / 32);
        sgemm_small_kernel<32, 64, 16, 4, 0><<<grid, 256>>>(
            p_xc, DI, W_x, 64, p_proj, nullptr, NTOK, 64, DI);
    }

    // 5) dt GEMM + softplus: (2048x32) @ (32x1024), A has lda=64 (dtr slice of proj)
    {
        dim3 grid(DI / 128, NTOK / 128);
        sgemm_kernel<128, 128, 8, 8, 8, 1><<<grid, 256>>>(
            p_proj, 64, W_dt, DI, p_dt, b_dt, NTOK, DI, DTR);
    }

    // 6) selective scan + gate
    scan_kernel<<<BB * DI / 16, 256>>>(p_dt, p_xc, p_proj, p_xz, A_log, D_param, p_y);

    // 7) out GEMM + transposed residual write: (2048x1024) @ (1024x512) + x
    {
        dim3 grid(CC / 64, NTOK / 64);
        sgemm_kernel<64, 64, 16, 4, 4, 2><<<grid, 256>>>(
            p_y, DI, W_out, CC, out, x, NTOK, CC, DI);
    }
}

// round 6
// speedup vs baseline: 3.5035x; 3.5035x over previous
#include <cuda_runtime.h>
#include <cuda_bf16.h>
#include <mma.h>

using namespace nvcuda;

// Problem constants (fixed shapes)
#define BB 2
#define CC 512
#define LL 1024            // D*H*W
#define DI 1024            // D_INNER
#define NS 16              // D_STATE
#define DTR 32             // DT_RANK
#define NTOK (BB*LL)       // 2048 tokens

// ---------------- scratch (device globals) ----------------
__device__ __nv_bfloat16 g_xnT[CC * NTOK];     // 2 MB  LN output, TRANSPOSED [c][t], bf16
__device__ float         g_xz[NTOK * 2 * DI];  // 16 MB in-proj output (xi | z)
__device__ float         g_xc[NTOK * DI];      // 8 MB  conv+silu output
__device__ float         g_proj[NTOK * 64];    // 0.5MB x-proj output (dtr|B|C)
__device__ float         g_dt[NTOK * DI];      // 8 MB  softplus(dt)
__device__ __nv_bfloat16 g_ybf[NTOK * DI];     // 4 MB  gated scan output, bf16
__device__ __nv_bfloat16 g_Win_bf[CC * 2 * DI];   // 2 MB
__device__ __nv_bfloat16 g_Wout_bf[DI * CC];      // 1 MB

// ---------------- fp32 -> bf16 convert ----------------
__global__ __launch_bounds__(256) void f2bf_kernel(const float* __restrict__ in,
                                                   __nv_bfloat16* __restrict__ out, int n)
{
    int i = (blockIdx.x * 256 + threadIdx.x) * 4;
    if (i < n) {
        float4 v = *reinterpret_cast<const float4*>(&in[i]);
        out[i + 0] = __float2bfloat16(v.x);
        out[i + 1] = __float2bfloat16(v.y);
        out[i + 2] = __float2bfloat16(v.z);
        out[i + 3] = __float2bfloat16(v.w);
    }
}

// ---------------- LayerNorm v2: coalesced reads, transposed bf16 write ----------------
// grid = BB * (LL/32) = 64 blocks; block = 256 threads = 32 l-lanes x 8 channel-groups.
__global__ __launch_bounds__(256) void ln_kernel(const float* __restrict__ x,
                                                 const float* __restrict__ gamma,
                                                 const float* __restrict__ beta,
                                                 __nv_bfloat16* __restrict__ xnT)
{
    int bx = blockIdx.x;
    int b  = bx >> 5;
    int l0 = (bx & 31) * 32;
    int tid  = threadIdx.x;
    int lane = tid & 31;     // l offset
    int cg   = tid >> 5;     // channel group 0..7 (covers 64 channels each)

    const float* xb = x + (size_t)b * CC * LL + l0 + lane;
    float vv[64];
    float s = 0.f, q = 0.f;
    #pragma unroll
    for (int i = 0; i < 64; i++) {
        int c = cg * 64 + i;
        float v = xb[(size_t)c * LL];      // coalesced along lane
        vv[i] = v;
        s += v; q += v * v;
    }
    __shared__ float red_s[8][32], red_q[8][32];
    red_s[cg][lane] = s; red_q[cg][lane] = q;
    __syncthreads();
    float ts = 0.f, tq = 0.f;
    #pragma unroll
    for (int g = 0; g < 8; g++) { ts += red_s[g][lane]; tq += red_q[g][lane]; }
    float mu  = ts * (1.f / CC);
    float var = tq * (1.f / CC) - mu * mu;
    float rs  = rsqrtf(var + 1e-5f);

    int t = b * LL + l0 + lane;
    #pragma unroll
    for (int i = 0; i < 64; i++) {
        int c = cg * 64 + i;
        float v = (vv[i] - mu) * rs * gamma[c] + beta[c];
        xnT[(size_t)c * NTOK + t] = __float2bfloat16(v);   // coalesced along lane
    }
}

// ---------------- wmma GEMM, A col-major (from xnT), plain fp32 store ----------------
// C[M,N] = A[M,K] @ B[K,N]; AT is [K][M] bf16, B is [K][N] bf16.
template<int BM, int BN, int BK, int WGM, int WGN>
__global__ __launch_bounds__(256) void mma_gemm_acol(const __nv_bfloat16* __restrict__ AT,
                                                     const __nv_bfloat16* __restrict__ B,
                                                     float* __restrict__ C,
                                                     int M, int N, int K)
{
    constexpr int LDA = BM + 8;
    constexpr int LDB = BN + 8;
    __shared__ __nv_bfloat16 As[BK * LDA];
    __shared__ __nv_bfloat16 Bs[BK * LDB];
    const int tid = threadIdx.x;
    const int wid = tid >> 5;
    const int m0 = blockIdx.y * BM;
    const int n0 = blockIdx.x * BN;
    const int wm = wid % WGM, wn = wid / WGM;
    constexpr int WTM = BM / WGM;           // 64
    constexpr int WTN = BN / WGN;           // 32
    constexpr int FM = WTM / 16, FN = WTN / 16;

    wmma::fragment<wmma::accumulator, 16, 16, 16, float> acc[FM][FN];
    #pragma unroll
    for (int i = 0; i < FM; i++)
        #pragma unroll
        for (int j = 0; j < FN; j++) wmma::fill_fragment(acc[i][j], 0.f);

    for (int k0 = 0; k0 < K; k0 += BK) {
        #pragma unroll
        for (int i = tid * 8; i < BK * BM; i += 256 * 8) {
            int r = i / BM, c = i % BM;
            *reinterpret_cast<uint4*>(&As[r * LDA + c]) =
                *reinterpret_cast<const uint4*>(&AT[(size_t)(k0 + r) * M + m0 + c]);
        }
        #pragma unroll
        for (int i = tid * 8; i < BK * BN; i += 256 * 8) {
            int r = i / BN, c = i % BN;
            *reinterpret_cast<uint4*>(&Bs[r * LDB + c]) =
                *reinterpret_cast<const uint4*>(&B[(size_t)(k0 + r) * N + n0 + c]);
        }
        __syncthreads();
        #pragma unroll
        for (int kk = 0; kk < BK; kk += 16) {
            wmma::fragment<wmma::matrix_a, 16, 16, 16, __nv_bfloat16, wmma::col_major> af[FM];
            wmma::fragment<wmma::matrix_b, 16, 16, 16, __nv_bfloat16, wmma::row_major> bf[FN];
            #pragma unroll
            for (int i = 0; i < FM; i++)
                wmma::load_matrix_sync(af[i], &As[kk * LDA + wm * WTM + i * 16], LDA);
            #pragma unroll
            for (int j = 0; j < FN; j++)
                wmma::load_matrix_sync(bf[j], &Bs[kk * LDB + wn * WTN + j * 16], LDB);
            #pragma unroll
            for (int i = 0; i < FM; i++)
                #pragma unroll
                for (int j = 0; j < FN; j++)
                    wmma::mma_sync(acc[i][j], af[i], bf[j], acc[i][j]);
        }
        __syncthreads();
    }
    #pragma unroll
    for (int i = 0; i < FM; i++)
        #pragma unroll
        for (int j = 0; j < FN; j++)
            wmma::store_matrix_sync(&C[(size_t)(m0 + wm * WTM + i * 16) * N + n0 + wn * WTN + j * 16],
                                    acc[i][j], N, wmma::mem_row_major);
}

// ---------------- wmma GEMM, A row-major, fused transposed residual epilogue ----------------
// out[b][n][l] = (A@B)[m][n] + x[b][n][l],  m = b*LL + l.  128 threads, 4 warps.
template<int BM, int BN, int BK>
__global__ __launch_bounds__(128) void mma_gemm_arow_res(const __nv_bfloat16* __restrict__ A,
                                                         const __nv_bfloat16* __restrict__ B,
                                                         float* __restrict__ out,
                                                         const float* __restrict__ x,
                                                         int M, int N, int K)
{
    constexpr int WGM = 2, WGN = 2;
    constexpr int LDA = BK + 8;       // 40
    constexpr int LDB = BN + 8;       // 72
    constexpr int LDC = BM + 4;       // 68
    constexpr int ASZ = BM * LDA * 2;             // bytes
    constexpr int BSZ = BK * LDB * 2;
    constexpr int CSZ = BN * LDC * 4;
    constexpr int SMEM = (ASZ + BSZ) > CSZ ? (ASZ + BSZ) : CSZ;
    __shared__ __align__(16) unsigned char sraw[SMEM];
    __nv_bfloat16* As = reinterpret_cast<__nv_bfloat16*>(sraw);
    __nv_bfloat16* Bs = reinterpret_cast<__nv_bfloat16*>(sraw + ASZ);
    float* Cs = reinterpret_cast<float*>(sraw);

    const int tid = threadIdx.x;
    const int wid = tid >> 5;
    const int m0 = blockIdx.y * BM;
    const int n0 = blockIdx.x * BN;
    const int wm = wid % WGM, wn = wid / WGM;
    constexpr int WTM = BM / WGM;     // 32
    constexpr int WTN = BN / WGN;     // 32
    constexpr int FM = WTM / 16, FN = WTN / 16;   // 2 x 2

    wmma::fragment<wmma::accumulator, 16, 16, 16, float> acc[FM][FN];
    #pragma unroll
    for (int i = 0; i < FM; i++)
        #pragma unroll
        for (int j = 0; j < FN; j++) wmma::fill_fragment(acc[i][j], 0.f);

    for (int k0 = 0; k0 < K; k0 += BK) {
        #pragma unroll
        for (int i = tid * 8; i < BM * BK; i += 128 * 8) {
            int r = i / BK, c = i % BK;
            *reinterpret_cast<uint4*>(&As[r * LDA + c]) =
                *reinterpret_cast<const uint4*>(&A[(size_t)(m0 + r) * K + k0 + c]);
        }
        #pragma unroll
        for (int i = tid * 8; i < BK * BN; i += 128 * 8) {
            int r = i / BN, c = i % BN;
            *reinterpret_cast<uint4*>(&Bs[r * LDB + c]) =
                *reinterpret_cast<const uint4*>(&B[(size_t)(k0 + r) * N + n0 + c]);
        }
        __syncthreads();
        #pragma unroll
        for (int kk = 0; kk < BK; kk += 16) {
            wmma::fragment<wmma::matrix_a, 16, 16, 16, __nv_bfloat16, wmma::row_major> af[FM];
            wmma::fragment<wmma::matrix_b, 16, 16, 16, __nv_bfloat16, wmma::row_major> bf[FN];
            #pragma unroll
            for (int i = 0; i < FM; i++)
                wmma::load_matrix_sync(af[i], &As[(wm * WTM + i * 16) * LDA + kk], LDA);
            #pragma unroll
            for (int j = 0; j < FN; j++)
                wmma::load_matrix_sync(bf[j], &Bs[kk * LDB + wn * WTN + j * 16], LDB);
            #pragma unroll
            for (int i = 0; i < FM; i++)
                #pragma unroll
                for (int j = 0; j < FN; j++)
                    wmma::mma_sync(acc[i][j], af[i], bf[j], acc[i][j]);
        }
        __syncthreads();
    }

    // stage C tile to smem col-major: Cs[n][m]
    #pragma unroll
    for (int i = 0; i < FM; i++)
        #pragma unroll
        for (int j = 0; j < FN; j++)
            wmma::store_matrix_sync(&Cs[(wn * WTN + j * 16) * LDC + wm * WTM + i * 16],
                                    acc[i][j], LDC, wmma::mem_col_major);
    __syncthreads();

    int b   = m0 >> 10;
    int l0b = m0 & (LL - 1);
    for (int idx = tid; idx < BM * BN; idx += 128) {
        int n = idx / BM;
        int m = idx % BM;           // lanes vary m -> coalesced global, conflict-free smem
        size_t gi = ((size_t)(b * CC + n0 + n)) * LL + l0b + m;
        out[gi] = Cs[n * LDC + m] + x[gi];
    }
}

// ---------------- causal depthwise conv (k=4) + SiLU ----------------
__global__ __launch_bounds__(256) void conv_silu_kernel(const float* __restrict__ xz,
                                                        const float* __restrict__ conv_w,
                                                        const float* __restrict__ conv_b,
                                                        float* __restrict__ xc)
{
    int idx = blockIdx.x * 256 + threadIdx.x;   // over NTOK*DI
    int d = idx & (DI - 1);
    int t = idx >> 10;
    int l = t & (LL - 1);
    float v = conv_b[d];
    const float* w = &conv_w[d * 4];
    #pragma unroll
    for (int k = 0; k < 4; ++k) {
        int ll = l - 3 + k;
        if (ll >= 0) v = fmaf(w[k], xz[(size_t)(t - 3 + k) * (2 * DI) + d], v);
    }
    float sg = 1.f / (1.f + __expf(-v));
    xc[idx] = v * sg;
}

// ---------------- x-proj: (2048x1024)@(1024x64), 4 tokens/block, 4-way K split ----------------
__global__ __launch_bounds__(256) void xproj_kernel(const float* __restrict__ xc,
                                                    const float* __restrict__ Wx,
                                                    float* __restrict__ proj)
{
    __shared__ float As[4 * 1024];          // 16 KB
    __shared__ float ps[4][4][64];          // [kgroup][token][col]
    int tid = threadIdx.x;
    int t0 = blockIdx.x * 4;
    const float* src = xc + (size_t)t0 * DI;
    #pragma unroll
    for (int i = tid * 4; i < 4096; i += 1024)
        *reinterpret_cast<float4*>(&As[i]) = *reinterpret_cast<const float4*>(&src[i]);
    __syncthreads();

    int col = tid & 63, g = tid >> 6;
    float a0 = 0.f, a1 = 0.f, a2 = 0.f, a3 = 0.f;
    int kbase = g * 256;
    #pragma unroll 8
    for (int k = 0; k < 256; k++) {
        float bv = __ldg(&Wx[(kbase + k) * 64 + col]);
        a0 = fmaf(As[0 * 1024 + kbase + k], bv, a0);
        a1 = fmaf(As[1 * 1024 + kbase + k], bv, a1);
        a2 = fmaf(As[2 * 1024 + kbase + k], bv, a2);
        a3 = fmaf(As[3 * 1024 + kbase + k], bv, a3);
    }
    ps[g][0][col] = a0; ps[g][1][col] = a1; ps[g][2][col] = a2; ps[g][3][col] = a3;
    __syncthreads();
    int tl = tid >> 6;
    float r = ps[0][tl][col] + ps[1][tl][col] + ps[2][tl][col] + ps[3][tl][col];
    proj[(size_t)(t0 + tl) * 64 + col] = r;
}

// ---------------- dt GEMM + softplus (fp32, K=32) ----------------
template<int BM, int BN, int BK, int TM, int TN>
__global__ __launch_bounds__(256) void sgemm_dt_kernel(const float* __restrict__ A, int lda,
                                                       const float* __restrict__ B, int ldb,
                                                       float* __restrict__ Co,
                                                       const float* __restrict__ bias,
                                                       int M, int N, int K)
{
    __shared__ float As[BK][BM];
    __shared__ float Bs[BK][BN];
    const int tid = threadIdx.x;
    const int m0 = blockIdx.y * BM;
    const int n0 = blockIdx.x * BN;
    const int tcols = BN / TN;
    const int tr = tid / tcols, tc = tid % tcols;

    float acc[TM][TN];
    #pragma unroll
    for (int i = 0; i < TM; i++)
        #pragma unroll
        for (int j = 0; j < TN; j++) acc[i][j] = 0.f;

    for (int k0 = 0; k0 < K; k0 += BK) {
        for (int i = tid * 4; i < BM * BK; i += 256 * 4) {
            int r = i / BK, c = i % BK;
            float4 v = *reinterpret_cast<const float4*>(&A[(size_t)(m0 + r) * lda + k0 + c]);
            As[c + 0][r] = v.x; As[c + 1][r] = v.y;
            As[c + 2][r] = v.z; As[c + 3][r] = v.w;
        }
        for (int i = tid * 4; i < BK * BN; i += 256 * 4) {
            int r = i / BN, c = i % BN;
            *reinterpret_cast<float4*>(&Bs[r][c]) =
                *reinterpret_cast<const float4*>(&B[(size_t)(k0 + r) * ldb + n0 + c]);
        }
        __syncthreads();
        #pragma unroll
        for (int kk = 0; kk < BK; ++kk) {
            float ra[TM], rb[TN];
            #pragma unroll
            for (int i = 0; i < TM; i += 4) {
                float4 v = *reinterpret_cast<const float4*>(&As[kk][tr * TM + i]);
                ra[i] = v.x; ra[i + 1] = v.y; ra[i + 2] = v.z; ra[i + 3] = v.w;
            }
            #pragma unroll
            for (int j = 0; j < TN; j += 4) {
                float4 v = *reinterpret_cast<const float4*>(&Bs[kk][tc * TN + j]);
                rb[j] = v.x; rb[j + 1] = v.y; rb[j + 2] = v.z; rb[j + 3] = v.w;
            }
            #pragma unroll
            for (int i = 0; i < TM; i++)
                #pragma unroll
                for (int j = 0; j < TN; j++)
                    acc[i][j] = fmaf(ra[i], rb[j], acc[i][j]);
        }
        __syncthreads();
    }
    #pragma unroll
    for (int i = 0; i < TM; i++) {
        int m = m0 + tr * TM + i;
        #pragma unroll
        for (int j = 0; j < TN; j++) {
            int n = n0 + tc * TN + j;
            float v = acc[i][j] + bias[n];
            Co[(size_t)m * N + n] = (v > 20.f) ? v : log1pf(__expf(v));
        }
    }
}

// ---------------- selective scan (unroll-4, bf16 gated output) ----------------
__global__ __launch_bounds__(256) void scan_kernel(const float* __restrict__ dt,
                                                   const float* __restrict__ xc,
                                                   const float* __restrict__ proj,
                                                   const float* __restrict__ xz,
                                                   const float* __restrict__ A_log,
                                                   const float* __restrict__ D_param,
                                                   __nv_bfloat16* __restrict__ y)
{
    int tid = threadIdx.x;
    int n = tid & 15;                       // state index
    int g = blockIdx.x * 16 + (tid >> 4);   // group = b*DI + d
    int b = g >> 10, d = g & (DI - 1);
    float a = -__expf(A_log[d * NS + n]);
    float Dp = D_param[d];
    float h = 0.f;
    int tbase = b * LL;
    for (int l = 0; l < LL; l += 4) {
        float dtv[4], xcv[4], Bv[4], Cv[4], zv[4];
        #pragma unroll
        for (int u = 0; u < 4; u++) {
            int t = tbase + l + u;
            dtv[u] = dt[(size_t)t * DI + d];
            xcv[u] = xc[(size_t)t * DI + d];
            Bv[u]  = proj[t * 64 + DTR + n];
            Cv[u]  = proj[t * 64 + DTR + NS + n];
            zv[u]  = xz[(size_t)t * (2 * DI) + DI + d];
        }
        #pragma unroll
        for (int u = 0; u < 4; u++) {
            float dA = __expf(dtv[u] * a);
            h = fmaf(dA, h, dtv[u] * xcv[u] * Bv[u]);
            float p = h * Cv[u];
            p += __shfl_xor_sync(0xffffffffu, p, 8);
            p += __shfl_xor_sync(0xffffffffu, p, 4);
            p += __shfl_xor_sync(0xffffffffu, p, 2);
            p += __shfl_xor_sync(0xffffffffu, p, 1);
            if (n == 0) {
                int t = tbase + l + u;
                float sg = 1.f / (1.f + __expf(-zv[u]));
                y[(size_t)t * DI + d] =
                    __float2bfloat16((p + Dp * xcv[u]) * (zv[u] * sg));
            }
        }
    }
}

// ---------------- launch ----------------
extern "C" void kernel_launch(void* const* d_in, const int* in_sizes, int n_in,
                              void* d_out, int out_size)
{
    const float* x       = (const float*)d_in[0];
    const float* gamma   = (const float*)d_in[1];
    const float* beta    = (const float*)d_in[2];
    const float* W_in    = (const float*)d_in[3];
    const float* conv_w  = (const float*)d_in[4];
    const float* conv_b  = (const float*)d_in[5];
    const float* W_x     = (const float*)d_in[6];
    const float* W_dt    = (const float*)d_in[7];
    const float* b_dt    = (const float*)d_in[8];
    const float* A_log   = (const float*)d_in[9];
    const float* D_param = (const float*)d_in[10];
    const float* W_out   = (const float*)d_in[11];
    float* out = (float*)d_out;

    __nv_bfloat16 *p_xnT, *p_ybf, *p_Win, *p_Wout;
    float *p_xz, *p_xc, *p_proj, *p_dt;
    cudaGetSymbolAddress((void**)&p_xnT, g_xnT);
    cudaGetSymbolAddress((void**)&p_xz,  g_xz);
    cudaGetSymbolAddress((void**)&p_xc,  g_xc);
    cudaGetSymbolAddress((void**)&p_proj,g_proj);
    cudaGetSymbolAddress((void**)&p_dt,  g_dt);
    cudaGetSymbolAddress((void**)&p_ybf, g_ybf);
    cudaGetSymbolAddress((void**)&p_Win, g_Win_bf);
    cudaGetSymbolAddress((void**)&p_Wout,g_Wout_bf);

    // 0) weight converts (bf16)
    f2bf_kernel<<<(CC * 2 * DI) / 1024, 256>>>(W_in,  p_Win,  CC * 2 * DI);
    f2bf_kernel<<<(DI * CC) / 1024, 256>>>(W_out, p_Wout, DI * CC);

    // 1) LayerNorm -> xnT bf16 [c][t]
    ln_kernel<<<BB * (LL / 32), 256>>>(x, gamma, beta, p_xnT);

    // 2) in-proj: (2048x512)@(512x2048) bf16 tensor-core, A col-major
    {
        dim3 grid((2 * DI) / 128, NTOK / 128);   // 16 x 16
        mma_gemm_acol<128, 128, 32, 2, 4><<<grid, 256>>>(
            p_xnT, p_Win, p_xz, NTOK, 2 * DI, CC);
    }

    // 3) causal conv + SiLU
    conv_silu_kernel<<<NTOK * DI / 256, 256>>>(p_xz, conv_w, conv_b, p_xc);

    // 4) x-proj: (2048x1024)@(1024x64)
    xproj_kernel<<<NTOK / 4, 256>>>(p_xc, W_x, p_proj);

    // 5) dt GEMM + softplus: (2048x32)@(32x1024)
    {
        dim3 grid(DI / 128, NTOK / 128);
        sgemm_dt_kernel<128, 128, 8, 8, 8><<<grid, 256>>>(
            p_proj, 64, W_dt, DI, p_dt, b_dt, NTOK, DI, DTR);
    }

    // 6) selective scan + gate -> y bf16
    scan_kernel<<<BB * DI / 16, 256>>>(p_dt, p_xc, p_proj, p_xz, A_log, D_param, p_ybf);

    // 7) out-proj: (2048x1024)@(1024x512) bf16 tensor-core + transposed residual
    {
        dim3 grid(CC / 64, NTOK / 64);           // 8 x 32
        mma_gemm_arow_res<64, 64, 32><<<grid, 128>>>(
            p_ybf, p_Wout, out, x, NTOK, CC, DI);
    }
}

// round 8
// speedup vs baseline: 3.5507x; 1.0135x over previous
#include <cuda_runtime.h>
#include <cuda_bf16.h>
#include <mma.h>

using namespace nvcuda;

#define BB 2
#define CC 512
#define LL 1024
#define DI 1024
#define NS 16
#define DTR 32
#define NTOK (BB*LL)

// ---------------- scratch ----------------
__device__ __nv_bfloat16 g_xnT[CC * NTOK];     // LN output, [c][t], bf16
__device__ float         g_xz[NTOK * 2 * DI];
__device__ float         g_xc[NTOK * DI];
__device__ float         g_proj[NTOK * 64];
__device__ float         g_dt[NTOK * DI];
__device__ __nv_bfloat16 g_ybf[NTOK * DI];
__device__ __nv_bfloat16 g_Win_bf[CC * 2 * DI];
__device__ __nv_bfloat16 g_Wout_bf[DI * CC];

// ---------------- fp32 -> bf16 ----------------
__global__ __launch_bounds__(256) void f2bf_kernel(const float* __restrict__ in,
                                                   __nv_bfloat16* __restrict__ out, int n)
{
    int i = (blockIdx.x * 256 + threadIdx.x) * 4;
    if (i < n) {
        float4 v = *reinterpret_cast<const float4*>(&in[i]);
        out[i + 0] = __float2bfloat16(v.x);
        out[i + 1] = __float2bfloat16(v.y);
        out[i + 2] = __float2bfloat16(v.z);
        out[i + 3] = __float2bfloat16(v.w);
    }
}

// ---------------- LayerNorm v3: 1024 threads/block, 16 ch/thread ----------------
// grid = BB*(LL/32) = 64; block = 1024 = 32 l-lanes x 32 channel-groups(16 ch each)
__global__ __launch_bounds__(1024) void ln_kernel(const float* __restrict__ x,
                                                  const float* __restrict__ gamma,
                                                  const float* __restrict__ beta,
                                                  __nv_bfloat16* __restrict__ xnT)
{
    int bx = blockIdx.x;
    int b  = bx >> 5;
    int l0 = (bx & 31) * 32;
    int tid  = threadIdx.x;
    int lane = tid & 31;
    int cg   = tid >> 5;           // 0..31, 16 channels each

    const float* xb = x + (size_t)b * CC * LL + l0 + lane;
    float vv[16];
    float s = 0.f, q = 0.f;
    #pragma unroll
    for (int i = 0; i < 16; i++) {
        int c = cg * 16 + i;
        float v = xb[(size_t)c * LL];          // coalesced along lane
        vv[i] = v;
        s += v; q += v * v;
    }
    __shared__ float red_s[32][32], red_q[32][32];
    red_s[cg][lane] = s; red_q[cg][lane] = q;
    __syncthreads();
    float ts = 0.f, tq = 0.f;
    #pragma unroll
    for (int g = 0; g < 32; g++) { ts += red_s[g][lane]; tq += red_q[g][lane]; }
    float mu  = ts * (1.f / CC);
    float var = tq * (1.f / CC) - mu * mu;
    float rs  = rsqrtf(var + 1e-5f);

    int t = b * LL + l0 + lane;
    #pragma unroll
    for (int i = 0; i < 16; i++) {
        int c = cg * 16 + i;
        float v = (vv[i] - mu) * rs * gamma[c] + beta[c];
        xnT[(size_t)c * NTOK + t] = __float2bfloat16(v);
    }
}

// ---------------- in-proj wmma, A col-major, reg double-buffered ----------------
// BM=BN=128, BK=32, 256 threads, warps 2x4 (warp tile 64x32)
__global__ __launch_bounds__(256) void mma_gemm_acol(const __nv_bfloat16* __restrict__ AT,
                                                     const __nv_bfloat16* __restrict__ B,
                                                     float* __restrict__ C,
                                                     int M, int N, int K)
{
    constexpr int BM = 128, BN = 128, BK = 32;
    constexpr int LDA = BM + 8, LDB = BN + 8;
    __shared__ __nv_bfloat16 As[BK * LDA];
    __shared__ __nv_bfloat16 Bs[BK * LDB];
    const int tid = threadIdx.x;
    const int wid = tid >> 5;
    const int m0 = blockIdx.y * BM;
    const int n0 = blockIdx.x * BN;
    const int wm = wid & 1, wn = wid >> 1;   // 2 x 4
    constexpr int WTM = 64, WTN = 32;
    constexpr int FM = 4, FN = 2;

    const int ar0 = tid >> 4, ac = (tid & 15) * 8;
    const int ar1 = ar0 + 16;

    wmma::fragment<wmma::accumulator, 16, 16, 16, float> acc[FM][FN];
    #pragma unroll
    for (int i = 0; i < FM; i++)
        #pragma unroll
        for (int j = 0; j < FN; j++) wmma::fill_fragment(acc[i][j], 0.f);

    uint4 pa0 = *reinterpret_cast<const uint4*>(&AT[(size_t)ar0 * M + m0 + ac]);
    uint4 pa1 = *reinterpret_cast<const uint4*>(&AT[(size_t)ar1 * M + m0 + ac]);
    uint4 pb0 = *reinterpret_cast<const uint4*>(&B[(size_t)ar0 * N + n0 + ac]);
    uint4 pb1 = *reinterpret_cast<const uint4*>(&B[(size_t)ar1 * N + n0 + ac]);
    *reinterpret_cast<uint4*>(&As[ar0 * LDA + ac]) = pa0;
    *reinterpret_cast<uint4*>(&As[ar1 * LDA + ac]) = pa1;
    *reinterpret_cast<uint4*>(&Bs[ar0 * LDB + ac]) = pb0;
    *reinterpret_cast<uint4*>(&Bs[ar1 * LDB + ac]) = pb1;
    __syncthreads();

    for (int k0 = 0; k0 < K; k0 += BK) {
        int kn = k0 + BK;
        if (kn < K) {
            pa0 = *reinterpret_cast<const uint4*>(&AT[(size_t)(kn + ar0) * M + m0 + ac]);
            pa1 = *reinterpret_cast<const uint4*>(&AT[(size_t)(kn + ar1) * M + m0 + ac]);
            pb0 = *reinterpret_cast<const uint4*>(&B[(size_t)(kn + ar0) * N + n0 + ac]);
            pb1 = *reinterpret_cast<const uint4*>(&B[(size_t)(kn + ar1) * N + n0 + ac]);
        }
        #pragma unroll
        for (int kk = 0; kk < BK; kk += 16) {
            wmma::fragment<wmma::matrix_a, 16, 16, 16, __nv_bfloat16, wmma::col_major> af[FM];
            wmma::fragment<wmma::matrix_b, 16, 16, 16, __nv_bfloat16, wmma::row_major> bf[FN];
            #pragma unroll
            for (int i = 0; i < FM; i++)
                wmma::load_matrix_sync(af[i], &As[kk * LDA + wm * WTM + i * 16], LDA);
            #pragma unroll
            for (int j = 0; j < FN; j++)
                wmma::load_matrix_sync(bf[j], &Bs[kk * LDB + wn * WTN + j * 16], LDB);
            #pragma unroll
            for (int i = 0; i < FM; i++)
                #pragma unroll
                for (int j = 0; j < FN; j++)
                    wmma::mma_sync(acc[i][j], af[i], bf[j], acc[i][j]);
        }
        __syncthreads();
        if (kn < K) {
            *reinterpret_cast<uint4*>(&As[ar0 * LDA + ac]) = pa0;
            *reinterpret_cast<uint4*>(&As[ar1 * LDA + ac]) = pa1;
            *reinterpret_cast<uint4*>(&Bs[ar0 * LDB + ac]) = pb0;
            *reinterpret_cast<uint4*>(&Bs[ar1 * LDB + ac]) = pb1;
            __syncthreads();
        }
    }
    #pragma unroll
    for (int i = 0; i < FM; i++)
        #pragma unroll
        for (int j = 0; j < FN; j++)
            wmma::store_matrix_sync(&C[(size_t)(m0 + wm * WTM + i * 16) * N + n0 + wn * WTN + j * 16],
                                    acc[i][j], N, wmma::mem_row_major);
}

// ---------------- out-proj wmma v2: BM=128,BN=64,BK=32, 256 thr, fused residual ----------------
__global__ __launch_bounds__(256) void mma_gemm_arow_res(const __nv_bfloat16* __restrict__ A,
                                                         const __nv_bfloat16* __restrict__ B,
                                                         float* __restrict__ out,
                                                         const float* __restrict__ x,
                                                         int M, int N, int K)
{
    constexpr int BM = 128, BN = 64, BK = 32;
    constexpr int LDA = BK + 8;       // 40
    constexpr int LDB = BN + 8;       // 72
    constexpr int LDC = BM + 4;       // 132
    constexpr int ASZ = BM * LDA * 2;
    constexpr int BSZ = BK * LDB * 2;
    constexpr int CSZ = BN * LDC * 4;
    constexpr int SMEM = (ASZ + BSZ) > CSZ ? (ASZ + BSZ) : CSZ;
    __shared__ __align__(16) unsigned char sraw[SMEM];
    __nv_bfloat16* As = reinterpret_cast<__nv_bfloat16*>(sraw);
    __nv_bfloat16* Bs = reinterpret_cast<__nv_bfloat16*>(sraw + ASZ);
    float* Cs = reinterpret_cast<float*>(sraw);

    const int tid = threadIdx.x;
    const int wid = tid >> 5;
    const int m0 = blockIdx.y * BM;
    const int n0 = blockIdx.x * BN;
    const int wm = wid & 3, wn = wid >> 2;    // 4 x 2
    constexpr int WTM = 32, WTN = 32;
    constexpr int FM = 2, FN = 2;

    const int ar0 = tid >> 2, aco = (tid & 3) * 8;
    const int ar1 = ar0 + 64;
    const int br = tid >> 3, bc = (tid & 7) * 8;

    wmma::fragment<wmma::accumulator, 16, 16, 16, float> acc[FM][FN];
    #pragma unroll
    for (int i = 0; i < FM; i++)
        #pragma unroll
        for (int j = 0; j < FN; j++) wmma::fill_fragment(acc[i][j], 0.f);

    uint4 pa0 = *reinterpret_cast<const uint4*>(&A[(size_t)(m0 + ar0) * K + aco]);
    uint4 pa1 = *reinterpret_cast<const uint4*>(&A[(size_t)(m0 + ar1) * K + aco]);
    uint4 pb  = *reinterpret_cast<const uint4*>(&B[(size_t)br * N + n0 + bc]);
    *reinterpret_cast<uint4*>(&As[ar0 * LDA + aco]) = pa0;
    *reinterpret_cast<uint4*>(&As[ar1 * LDA + aco]) = pa1;
    *reinterpret_cast<uint4*>(&Bs[br * LDB + bc])   = pb;
    __syncthreads();

    for (int k0 = 0; k0 < K; k0 += BK) {
        int kn = k0 + BK;
        if (kn < K) {
            pa0 = *reinterpret_cast<const uint4*>(&A[(size_t)(m0 + ar0) * K + kn + aco]);
            pa1 = *reinterpret_cast<const uint4*>(&A[(size_t)(m0 + ar1) * K + kn + aco]);
            pb  = *reinterpret_cast<const uint4*>(&B[(size_t)(kn + br) * N + n0 + bc]);
        }
        #pragma unroll
        for (int kk = 0; kk < BK; kk += 16) {
            wmma::fragment<wmma::matrix_a, 16, 16, 16, __nv_bfloat16, wmma::row_major> af[FM];
            wmma::fragment<wmma::matrix_b, 16, 16, 16, __nv_bfloat16, wmma::row_major> bf[FN];
            #pragma unroll
            for (int i = 0; i < FM; i++)
                wmma::load_matrix_sync(af[i], &As[(wm * WTM + i * 16) * LDA + kk], LDA);
            #pragma unroll
            for (int j = 0; j < FN; j++)
                wmma::load_matrix_sync(bf[j], &Bs[kk * LDB + wn * WTN + j * 16], LDB);
            #pragma unroll
            for (int i = 0; i < FM; i++)
                #pragma unroll
                for (int j = 0; j < FN; j++)
                    wmma::mma_sync(acc[i][j], af[i], bf[j], acc[i][j]);
        }
        __syncthreads();
        if (kn < K) {
            *reinterpret_cast<uint4*>(&As[ar0 * LDA + aco]) = pa0;
            *reinterpret_cast<uint4*>(&As[ar1 * LDA + aco]) = pa1;
            *reinterpret_cast<uint4*>(&Bs[br * LDB + bc])   = pb;
            __syncthreads();
        }
    }

    // stage C col-major in smem: Cs[n][m]
    #pragma unroll
    for (int i = 0; i < FM; i++)
        #pragma unroll
        for (int j = 0; j < FN; j++)
            wmma::store_matrix_sync(&Cs[(wn * WTN + j * 16) * LDC + wm * WTM + i * 16],
                                    acc[i][j], LDC, wmma::mem_col_major);
    __syncthreads();

    int b   = m0 >> 10;
    int l0b = m0 & (LL - 1);
    #pragma unroll
    for (int idx = tid; idx < BM * BN; idx += 256) {
        int n = idx / BM;
        int m = idx % BM;
        size_t gi = ((size_t)(b * CC + n0 + n)) * LL + l0b + m;
        out[gi] = Cs[n * LDC + m] + x[gi];
    }
}

// ---------------- causal conv (k=4) + SiLU, float4 over d ----------------
__global__ __launch_bounds__(256) void conv_silu_kernel(const float* __restrict__ xz,
                                                        const float* __restrict__ conv_w,
                                                        const float* __restrict__ conv_b,
                                                        float* __restrict__ xc)
{
    int idx4 = blockIdx.x * 256 + threadIdx.x;   // over NTOK*DI/4
    int d4 = (idx4 * 4) & (DI - 1);
    int t  = (idx4 * 4) >> 10;
    int l  = t & (LL - 1);
    float4 v = *reinterpret_cast<const float4*>(&conv_b[d4]);
    float w_[4][4];
    #pragma unroll
    for (int i = 0; i < 4; i++) {
        float4 wr = *reinterpret_cast<const float4*>(&conv_w[(d4 + i) * 4]);
        w_[i][0] = wr.x; w_[i][1] = wr.y; w_[i][2] = wr.z; w_[i][3] = wr.w;
    }
    #pragma unroll
    for (int k = 0; k < 4; ++k) {
        if (l - 3 + k >= 0) {
            float4 xr = *reinterpret_cast<const float4*>(&xz[(size_t)(t - 3 + k) * (2 * DI) + d4]);
            v.x = fmaf(w_[0][k], xr.x, v.x);
            v.y = fmaf(w_[1][k], xr.y, v.y);
            v.z = fmaf(w_[2][k], xr.z, v.z);
            v.w = fmaf(w_[3][k], xr.w, v.w);
        }
    }
    v.x *= 1.f / (1.f + __expf(-v.x));
    v.y *= 1.f / (1.f + __expf(-v.y));
    v.z *= 1.f / (1.f + __expf(-v.z));
    v.w *= 1.f / (1.f + __expf(-v.w));
    *reinterpret_cast<float4*>(&xc[(size_t)idx4 * 4]) = v;
}

// ---------------- x-proj: 8 tokens/block, 4-way K split ----------------
__global__ __launch_bounds__(256) void xproj_kernel(const float* __restrict__ xc,
                                                    const float* __restrict__ Wx,
                                                    float* __restrict__ proj)
{
    __shared__ float As[8 * 1024];          // 32 KB
    __shared__ float ps[4][8][64];          // 8 KB
    int tid = threadIdx.x;
    int t0 = blockIdx.x * 8;
    const float* src = xc + (size_t)t0 * DI;
    #pragma unroll
    for (int i = tid * 4; i < 8192; i += 1024)
        *reinterpret_cast<float4*>(&As[i]) = *reinterpret_cast<const float4*>(&src[i]);
    __syncthreads();

    int col = tid & 63, g = tid >> 6;
    int kbase = g * 256;
    float acc[8];
    #pragma unroll
    for (int i = 0; i < 8; i++) acc[i] = 0.f;
    #pragma unroll 4
    for (int k = 0; k < 256; k++) {
        float bv = __ldg(&Wx[(kbase + k) * 64 + col]);
        #pragma unroll
        for (int tok = 0; tok < 8; tok++)
            acc[tok] = fmaf(As[tok * 1024 + kbase + k], bv, acc[tok]);
    }
    #pragma unroll
    for (int tok = 0; tok < 8; tok++) ps[g][tok][col] = acc[tok];
    __syncthreads();
    #pragma unroll
    for (int j = 0; j < 2; j++) {
        int tok = (tid >> 6) + 4 * j;
        float r = ps[0][tok][col] + ps[1][tok][col] + ps[2][tok][col] + ps[3][tok][col];
        proj[(size_t)(t0 + tok) * 64 + col] = r;
    }
}

// ---------------- dt GEMM + softplus (fp32, K=32) ----------------
template<int BM, int BN, int BK, int TM, int TN>
__global__ __launch_bounds__(256) void sgemm_dt_kernel(const float* __restrict__ A, int lda,
                                                       const float* __restrict__ B, int ldb,
                                                       float* __restrict__ Co,
                                                       const float* __restrict__ bias,
                                                       int M, int N, int K)
{
    __shared__ float As[BK][BM];
    __shared__ float Bs[BK][BN];
    const int tid = threadIdx.x;
    const int m0 = blockIdx.y * BM;
    const int n0 = blockIdx.x * BN;
    const int tcols = BN / TN;
    const int tr = tid / tcols, tc = tid % tcols;

    float acc[TM][TN];
    #pragma unroll
    for (int i = 0; i < TM; i++)
        #pragma unroll
        for (int j = 0; j < TN; j++) acc[i][j] = 0.f;

    for (int k0 = 0; k0 < K; k0 += BK) {
        for (int i = tid * 4; i < BM * BK; i += 256 * 4) {
            int r = i / BK, c = i % BK;
            float4 v = *reinterpret_cast<const float4*>(&A[(size_t)(m0 + r) * lda + k0 + c]);
            As[c + 0][r] = v.x; As[c + 1][r] = v.y;
            As[c + 2][r] = v.z; As[c + 3][r] = v.w;
        }
        for (int i = tid * 4; i < BK * BN; i += 256 * 4) {
            int r = i / BN, c = i % BN;
            *reinterpret_cast<float4*>(&Bs[r][c]) =
                *reinterpret_cast<const float4*>(&B[(size_t)(k0 + r) * ldb + n0 + c]);
        }
        __syncthreads();
        #pragma unroll
        for (int kk = 0; kk < BK; ++kk) {
            float ra[TM], rb[TN];
            #pragma unroll
            for (int i = 0; i < TM; i += 4) {
                float4 v = *reinterpret_cast<const float4*>(&As[kk][tr * TM + i]);
                ra[i] = v.x; ra[i + 1] = v.y; ra[i + 2] = v.z; ra[i + 3] = v.w;
            }
            #pragma unroll
            for (int j = 0; j < TN; j += 4) {
                float4 v = *reinterpret_cast<const float4*>(&Bs[kk][tc * TN + j]);
                rb[j] = v.x; rb[j + 1] = v.y; rb[j + 2] = v.z; rb[j + 3] = v.w;
            }
            #pragma unroll
            for (int i = 0; i < TM; i++)
                #pragma unroll
                for (int j = 0; j < TN; j++)
                    acc[i][j] = fmaf(ra[i], rb[j], acc[i][j]);
        }
        __syncthreads();
    }
    #pragma unroll
    for (int i = 0; i < TM; i++) {
        int m = m0 + tr * TM + i;
        #pragma unroll
        for (int j = 0; j < TN; j++) {
            int n = n0 + tc * TN + j;
            float v = acc[i][j] + bias[n];
            Co[(size_t)m * N + n] = (v > 20.f) ? v : log1pf(__expf(v));
        }
    }
}

// ---------------- selective scan ----------------
__global__ __launch_bounds__(256) void scan_kernel(const float* __restrict__ dt,
                                                   const float* __restrict__ xc,
                                                   const float* __restrict__ proj,
                                                   const float* __restrict__ xz,
                                                   const float* __restrict__ A_log,
                                                   const float* __restrict__ D_param,
                                                   __nv_bfloat16* __restrict__ y)
{
    int tid = threadIdx.x;
    int n = tid & 15;
    int g = blockIdx.x * 16 + (tid >> 4);
    int b = g >> 10, d = g & (DI - 1);
    float a = -__expf(A_log[d * NS + n]);
    float Dp = D_param[d];
    float h = 0.f;
    int tbase = b * LL;
    for (int l = 0; l < LL; l += 4) {
        float dtv[4], xcv[4], Bv[4], Cv[4], zv[4];
        #pragma unroll
        for (int u = 0; u < 4; u++) {
            int t = tbase + l + u;
            dtv[u] = dt[(size_t)t * DI + d];
            xcv[u] = xc[(size_t)t * DI + d];
            Bv[u]  = proj[t * 64 + DTR + n];
            Cv[u]  = proj[t * 64 + DTR + NS + n];
            zv[u]  = xz[(size_t)t * (2 * DI) + DI + d];
        }
        #pragma unroll
        for (int u = 0; u < 4; u++) {
            float dA = __expf(dtv[u] * a);
            h = fmaf(dA, h, dtv[u] * xcv[u] * Bv[u]);
            float p = h * Cv[u];
            p += __shfl_xor_sync(0xffffffffu, p, 8);
            p += __shfl_xor_sync(0xffffffffu, p, 4);
            p += __shfl_xor_sync(0xffffffffu, p, 2);
            p += __shfl_xor_sync(0xffffffffu, p, 1);
            if (n == 0) {
                int t = tbase + l + u;
                float sg = 1.f / (1.f + __expf(-zv[u]));
                y[(size_t)t * DI + d] =
                    __float2bfloat16((p + Dp * xcv[u]) * (zv[u] * sg));
            }
        }
    }
}

// ---------------- launch ----------------
extern "C" void kernel_launch(void* const* d_in, const int* in_sizes, int n_in,
                              void* d_out, int out_size)
{
    const float* x       = (const float*)d_in[0];
    const float* gamma   = (const float*)d_in[1];
    const float* beta    = (const float*)d_in[2];
    const float* W_in    = (const float*)d_in[3];
    const float* conv_w  = (const float*)d_in[4];
    const float* conv_b  = (const float*)d_in[5];
    const float* W_x     = (const float*)d_in[6];
    const float* W_dt    = (const float*)d_in[7];
    const float* b_dt    = (const float*)d_in[8];
    const float* A_log   = (const float*)d_in[9];
    const float* D_param = (const float*)d_in[10];
    const float* W_out   = (const float*)d_in[11];
    float* out = (float*)d_out;

    __nv_bfloat16 *p_xnT, *p_ybf, *p_Win, *p_Wout;
    float *p_xz, *p_xc, *p_proj, *p_dt;
    cudaGetSymbolAddress((void**)&p_xnT, g_xnT);
    cudaGetSymbolAddress((void**)&p_xz,  g_xz);
    cudaGetSymbolAddress((void**)&p_xc,  g_xc);
    cudaGetSymbolAddress((void**)&p_proj,g_proj);
    cudaGetSymbolAddress((void**)&p_dt,  g_dt);
    cudaGetSymbolAddress((void**)&p_ybf, g_ybf);
    cudaGetSymbolAddress((void**)&p_Win, g_Win_bf);
    cudaGetSymbolAddress((void**)&p_Wout,g_Wout_bf);

    f2bf_kernel<<<(CC * 2 * DI) / 1024, 256>>>(W_in,  p_Win,  CC * 2 * DI);
    f2bf_kernel<<<(DI * CC) / 1024, 256>>>(W_out, p_Wout, DI * CC);

    ln_kernel<<<BB * (LL / 32), 1024>>>(x, gamma, beta, p_xnT);

    {   // in-proj (2048x512)@(512x2048)
        dim3 grid((2 * DI) / 128, NTOK / 128);
        mma_gemm_acol<<<grid, 256>>>(p_xnT, p_Win, p_xz, NTOK, 2 * DI, CC);
    }

    conv_silu_kernel<<<NTOK * DI / 1024, 256>>>(p_xz, conv_w, conv_b, p_xc);

    xproj_kernel<<<NTOK / 8, 256>>>(p_xc, W_x, p_proj);

    {   // dt GEMM + softplus
        dim3 grid(DI / 128, NTOK / 128);
        sgemm_dt_kernel<128, 128, 8, 8, 8><<<grid, 256>>>(
            p_proj, 64, W_dt, DI, p_dt, b_dt, NTOK, DI, DTR);
    }

    scan_kernel<<<BB * DI / 16, 256>>>(p_dt, p_xc, p_proj, p_xz, A_log, D_param, p_ybf);

    {   // out-proj (2048x1024)@(1024x512) + residual
        dim3 grid(CC / 64, NTOK / 128);
        mma_gemm_arow_res<<<grid, 256>>>(p_ybf, p_Wout, out, x, NTOK, CC, DI);
    }
}

// round 10
// speedup vs baseline: 6.4606x; 1.8195x over previous
#include <cuda_runtime.h>
#include <cuda_bf16.h>
#include <mma.h>

using namespace nvcuda;

#define BB 2
#define CC 512
#define LL 1024
#define DI 1024
#define NS 16
#define DTR 32
#define NTOK (BB*LL)
#define NCH 16           // scan chunks
#define CLEN 64          // chunk length (NCH*CLEN == LL)

// ---------------- scratch ----------------
__device__ __nv_bfloat16 g_xnT[CC * NTOK];
__device__ float         g_xz[NTOK * 2 * DI];
__device__ float         g_xc[NTOK * DI];
__device__ float         g_proj[NTOK * 64];
__device__ float         g_dt[NTOK * DI];
__device__ __nv_bfloat16 g_ybf[NTOK * DI];
__device__ __nv_bfloat16 g_Win_bf[CC * 2 * DI];
__device__ __nv_bfloat16 g_Wout_bf[DI * CC];
__device__ float         g_P [BB * DI * NCH * NS];   // 2 MB
__device__ float         g_H [BB * DI * NCH * NS];   // 2 MB
__device__ float         g_h0[BB * DI * NCH * NS];   // 2 MB

// ---------------- fp32 -> bf16 ----------------
__global__ __launch_bounds__(256) void f2bf_kernel(const float* __restrict__ in,
                                                   __nv_bfloat16* __restrict__ out, int n)
{
    int i = (blockIdx.x * 256 + threadIdx.x) * 4;
    if (i < n) {
        float4 v = *reinterpret_cast<const float4*>(&in[i]);
        out[i + 0] = __float2bfloat16(v.x);
        out[i + 1] = __float2bfloat16(v.y);
        out[i + 2] = __float2bfloat16(v.z);
        out[i + 3] = __float2bfloat16(v.w);
    }
}

// ---------------- LayerNorm: 1024 threads/block ----------------
__global__ __launch_bounds__(1024) void ln_kernel(const float* __restrict__ x,
                                                  const float* __restrict__ gamma,
                                                  const float* __restrict__ beta,
                                                  __nv_bfloat16* __restrict__ xnT)
{
    int bx = blockIdx.x;
    int b  = bx >> 5;
    int l0 = (bx & 31) * 32;
    int tid  = threadIdx.x;
    int lane = tid & 31;
    int cg   = tid >> 5;

    const float* xb = x + (size_t)b * CC * LL + l0 + lane;
    float vv[16];
    float s = 0.f, q = 0.f;
    #pragma unroll
    for (int i = 0; i < 16; i++) {
        int c = cg * 16 + i;
        float v = xb[(size_t)c * LL];
        vv[i] = v;
        s += v; q += v * v;
    }
    __shared__ float red_s[32][32], red_q[32][32];
    red_s[cg][lane] = s; red_q[cg][lane] = q;
    __syncthreads();
    float ts = 0.f, tq = 0.f;
    #pragma unroll
    for (int g = 0; g < 32; g++) { ts += red_s[g][lane]; tq += red_q[g][lane]; }
    float mu  = ts * (1.f / CC);
    float var = tq * (1.f / CC) - mu * mu;
    float rs  = rsqrtf(var + 1e-5f);

    int t = b * LL + l0 + lane;
    #pragma unroll
    for (int i = 0; i < 16; i++) {
        int c = cg * 16 + i;
        float v = (vv[i] - mu) * rs * gamma[c] + beta[c];
        xnT[(size_t)c * NTOK + t] = __float2bfloat16(v);
    }
}

// ---------------- in-proj wmma ----------------
__global__ __launch_bounds__(256) void mma_gemm_acol(const __nv_bfloat16* __restrict__ AT,
                                                     const __nv_bfloat16* __restrict__ B,
                                                     float* __restrict__ C,
                                                     int M, int N, int K)
{
    constexpr int BM = 128, BN = 128, BK = 32;
    constexpr int LDA = BM + 8, LDB = BN + 8;
    __shared__ __nv_bfloat16 As[BK * LDA];
    __shared__ __nv_bfloat16 Bs[BK * LDB];
    const int tid = threadIdx.x;
    const int wid = tid >> 5;
    const int m0 = blockIdx.y * BM;
    const int n0 = blockIdx.x * BN;
    const int wm = wid & 1, wn = wid >> 1;
    constexpr int WTM = 64, WTN = 32;
    constexpr int FM = 4, FN = 2;

    const int ar0 = tid >> 4, ac = (tid & 15) * 8;
    const int ar1 = ar0 + 16;

    wmma::fragment<wmma::accumulator, 16, 16, 16, float> acc[FM][FN];
    #pragma unroll
    for (int i = 0; i < FM; i++)
        #pragma unroll
        for (int j = 0; j < FN; j++) wmma::fill_fragment(acc[i][j], 0.f);

    uint4 pa0 = *reinterpret_cast<const uint4*>(&AT[(size_t)ar0 * M + m0 + ac]);
    uint4 pa1 = *reinterpret_cast<const uint4*>(&AT[(size_t)ar1 * M + m0 + ac]);
    uint4 pb0 = *reinterpret_cast<const uint4*>(&B[(size_t)ar0 * N + n0 + ac]);
    uint4 pb1 = *reinterpret_cast<const uint4*>(&B[(size_t)ar1 * N + n0 + ac]);
    *reinterpret_cast<uint4*>(&As[ar0 * LDA + ac]) = pa0;
    *reinterpret_cast<uint4*>(&As[ar1 * LDA + ac]) = pa1;
    *reinterpret_cast<uint4*>(&Bs[ar0 * LDB + ac]) = pb0;
    *reinterpret_cast<uint4*>(&Bs[ar1 * LDB + ac]) = pb1;
    __syncthreads();

    for (int k0 = 0; k0 < K; k0 += BK) {
        int kn = k0 + BK;
        if (kn < K) {
            pa0 = *reinterpret_cast<const uint4*>(&AT[(size_t)(kn + ar0) * M + m0 + ac]);
            pa1 = *reinterpret_cast<const uint4*>(&AT[(size_t)(kn + ar1) * M + m0 + ac]);
            pb0 = *reinterpret_cast<const uint4*>(&B[(size_t)(kn + ar0) * N + n0 + ac]);
            pb1 = *reinterpret_cast<const uint4*>(&B[(size_t)(kn + ar1) * N + n0 + ac]);
        }
        #pragma unroll
        for (int kk = 0; kk < BK; kk += 16) {
            wmma::fragment<wmma::matrix_a, 16, 16, 16, __nv_bfloat16, wmma::col_major> af[FM];
            wmma::fragment<wmma::matrix_b, 16, 16, 16, __nv_bfloat16, wmma::row_major> bf[FN];
            #pragma unroll
            for (int i = 0; i < FM; i++)
                wmma::load_matrix_sync(af[i], &As[kk * LDA + wm * WTM + i * 16], LDA);
            #pragma unroll
            for (int j = 0; j < FN; j++)
                wmma::load_matrix_sync(bf[j], &Bs[kk * LDB + wn * WTN + j * 16], LDB);
            #pragma unroll
            for (int i = 0; i < FM; i++)
                #pragma unroll
                for (int j = 0; j < FN; j++)
                    wmma::mma_sync(acc[i][j], af[i], bf[j], acc[i][j]);
        }
        __syncthreads();
        if (kn < K) {
            *reinterpret_cast<uint4*>(&As[ar0 * LDA + ac]) = pa0;
            *reinterpret_cast<uint4*>(&As[ar1 * LDA + ac]) = pa1;
            *reinterpret_cast<uint4*>(&Bs[ar0 * LDB + ac]) = pb0;
            *reinterpret_cast<uint4*>(&Bs[ar1 * LDB + ac]) = pb1;
            __syncthreads();
        }
    }
    #pragma unroll
    for (int i = 0; i < FM; i++)
        #pragma unroll
        for (int j = 0; j < FN; j++)
            wmma::store_matrix_sync(&C[(size_t)(m0 + wm * WTM + i * 16) * N + n0 + wn * WTN + j * 16],
                                    acc[i][j], N, wmma::mem_row_major);
}

// ---------------- out-proj wmma + fused transposed residual ----------------
__global__ __launch_bounds__(256) void mma_gemm_arow_res(const __nv_bfloat16* __restrict__ A,
                                                         const __nv_bfloat16* __restrict__ B,
                                                         float* __restrict__ out,
                                                         const float* __restrict__ x,
                                                         int M, int N, int K)
{
    constexpr int BM = 128, BN = 64, BK = 32;
    constexpr int LDA = BK + 8;
    constexpr int LDB = BN + 8;
    constexpr int LDC = BM + 4;
    constexpr int ASZ = BM * LDA * 2;
    constexpr int BSZ = BK * LDB * 2;
    constexpr int CSZ = BN * LDC * 4;
    constexpr int SMEM = (ASZ + BSZ) > CSZ ? (ASZ + BSZ) : CSZ;
    __shared__ __align__(16) unsigned char sraw[SMEM];
    __nv_bfloat16* As = reinterpret_cast<__nv_bfloat16*>(sraw);
    __nv_bfloat16* Bs = reinterpret_cast<__nv_bfloat16*>(sraw + ASZ);
    float* Cs = reinterpret_cast<float*>(sraw);

    const int tid = threadIdx.x;
    const int wid = tid >> 5;
    const int m0 = blockIdx.y * BM;
    const int n0 = blockIdx.x * BN;
    const int wm = wid & 3, wn = wid >> 2;
    constexpr int WTM = 32, WTN = 32;
    constexpr int FM = 2, FN = 2;

    const int ar0 = tid >> 2, aco = (tid & 3) * 8;
    const int ar1 = ar0 + 64;
    const int br = tid >> 3, bc = (tid & 7) * 8;

    wmma::fragment<wmma::accumulator, 16, 16, 16, float> acc[FM][FN];
    #pragma unroll
    for (int i = 0; i < FM; i++)
        #pragma unroll
        for (int j = 0; j < FN; j++) wmma::fill_fragment(acc[i][j], 0.f);

    uint4 pa0 = *reinterpret_cast<const uint4*>(&A[(size_t)(m0 + ar0) * K + aco]);
    uint4 pa1 = *reinterpret_cast<const uint4*>(&A[(size_t)(m0 + ar1) * K + aco]);
    uint4 pb  = *reinterpret_cast<const uint4*>(&B[(size_t)br * N + n0 + bc]);
    *reinterpret_cast<uint4*>(&As[ar0 * LDA + aco]) = pa0;
    *reinterpret_cast<uint4*>(&As[ar1 * LDA + aco]) = pa1;
    *reinterpret_cast<uint4*>(&Bs[br * LDB + bc])   = pb;
    __syncthreads();

    for (int k0 = 0; k0 < K; k0 += BK) {
        int kn = k0 + BK;
        if (kn < K) {
            pa0 = *reinterpret_cast<const uint4*>(&A[(size_t)(m0 + ar0) * K + kn + aco]);
            pa1 = *reinterpret_cast<const uint4*>(&A[(size_t)(m0 + ar1) * K + kn + aco]);
            pb  = *reinterpret_cast<const uint4*>(&B[(size_t)(kn + br) * N + n0 + bc]);
        }
        #pragma unroll
        for (int kk = 0; kk < BK; kk += 16) {
            wmma::fragment<wmma::matrix_a, 16, 16, 16, __nv_bfloat16, wmma::row_major> af[FM];
            wmma::fragment<wmma::matrix_b, 16, 16, 16, __nv_bfloat16, wmma::row_major> bf[FN];
            #pragma unroll
            for (int i = 0; i < FM; i++)
                wmma::load_matrix_sync(af[i], &As[(wm * WTM + i * 16) * LDA + kk], LDA);
            #pragma unroll
            for (int j = 0; j < FN; j++)
                wmma::load_matrix_sync(bf[j], &Bs[kk * LDB + wn * WTN + j * 16], LDB);
            #pragma unroll
            for (int i = 0; i < FM; i++)
                #pragma unroll
                for (int j = 0; j < FN; j++)
                    wmma::mma_sync(acc[i][j], af[i], bf[j], acc[i][j]);
        }
        __syncthreads();
        if (kn < K) {
            *reinterpret_cast<uint4*>(&As[ar0 * LDA + aco]) = pa0;
            *reinterpret_cast<uint4*>(&As[ar1 * LDA + aco]) = pa1;
            *reinterpret_cast<uint4*>(&Bs[br * LDB + bc])   = pb;
            __syncthreads();
        }
    }

    #pragma unroll
    for (int i = 0; i < FM; i++)
        #pragma unroll
        for (int j = 0; j < FN; j++)
            wmma::store_matrix_sync(&Cs[(wn * WTN + j * 16) * LDC + wm * WTM + i * 16],
                                    acc[i][j], LDC, wmma::mem_col_major);
    __syncthreads();

    int b   = m0 >> 10;
    int l0b = m0 & (LL - 1);
    #pragma unroll
    for (int idx = tid; idx < BM * BN; idx += 256) {
        int n = idx / BM;
        int m = idx % BM;
        size_t gi = ((size_t)(b * CC + n0 + n)) * LL + l0b + m;
        out[gi] = Cs[n * LDC + m] + x[gi];
    }
}

// ---------------- causal conv (k=4) + SiLU ----------------
__global__ __launch_bounds__(256) void conv_silu_kernel(const float* __restrict__ xz,
                                                        const float* __restrict__ conv_w,
                                                        const float* __restrict__ conv_b,
                                                        float* __restrict__ xc)
{
    int idx4 = blockIdx.x * 256 + threadIdx.x;
    int d4 = (idx4 * 4) & (DI - 1);
    int t  = (idx4 * 4) >> 10;
    int l  = t & (LL - 1);
    float4 v = *reinterpret_cast<const float4*>(&conv_b[d4]);
    float w_[4][4];
    #pragma unroll
    for (int i = 0; i < 4; i++) {
        float4 wr = *reinterpret_cast<const float4*>(&conv_w[(d4 + i) * 4]);
        w_[i][0] = wr.x; w_[i][1] = wr.y; w_[i][2] = wr.z; w_[i][3] = wr.w;
    }
    #pragma unroll
    for (int k = 0; k < 4; ++k) {
        if (l - 3 + k >= 0) {
            float4 xr = *reinterpret_cast<const float4*>(&xz[(size_t)(t - 3 + k) * (2 * DI) + d4]);
            v.x = fmaf(w_[0][k], xr.x, v.x);
            v.y = fmaf(w_[1][k], xr.y, v.y);
            v.z = fmaf(w_[2][k], xr.z, v.z);
            v.w = fmaf(w_[3][k], xr.w, v.w);
        }
    }
    v.x *= 1.f / (1.f + __expf(-v.x));
    v.y *= 1.f / (1.f + __expf(-v.y));
    v.z *= 1.f / (1.f + __expf(-v.z));
    v.w *= 1.f / (1.f + __expf(-v.w));
    *reinterpret_cast<float4*>(&xc[(size_t)idx4 * 4]) = v;
}

// ---------------- x-proj ----------------
__global__ __launch_bounds__(256) void xproj_kernel(const float* __restrict__ xc,
                                                    const float* __restrict__ Wx,
                                                    float* __restrict__ proj)
{
    __shared__ float As[8 * 1024];
    __shared__ float ps[4][8][64];
    int tid = threadIdx.x;
    int t0 = blockIdx.x * 8;
    const float* src = xc + (size_t)t0 * DI;
    #pragma unroll
    for (int i = tid * 4; i < 8192; i += 1024)
        *reinterpret_cast<float4*>(&As[i]) = *reinterpret_cast<const float4*>(&src[i]);
    __syncthreads();

    int col = tid & 63, g = tid >> 6;
    int kbase = g * 256;
    float acc[8];
    #pragma unroll
    for (int i = 0; i < 8; i++) acc[i] = 0.f;
    #pragma unroll 4
    for (int k = 0; k < 256; k++) {
        float bv = __ldg(&Wx[(kbase + k) * 64 + col]);
        #pragma unroll
        for (int tok = 0; tok < 8; tok++)
            acc[tok] = fmaf(As[tok * 1024 + kbase + k], bv, acc[tok]);
    }
    #pragma unroll
    for (int tok = 0; tok < 8; tok++) ps[g][tok][col] = acc[tok];
    __syncthreads();
    #pragma unroll
    for (int j = 0; j < 2; j++) {
        int tok = (tid >> 6) + 4 * j;
        float r = ps[0][tok][col] + ps[1][tok][col] + ps[2][tok][col] + ps[3][tok][col];
        proj[(size_t)(t0 + tok) * 64 + col] = r;
    }
}

// ---------------- dt GEMM + softplus ----------------
template<int BM, int BN, int BK, int TM, int TN>
__global__ __launch_bounds__(256) void sgemm_dt_kernel(const float* __restrict__ A, int lda,
                                                       const float* __restrict__ B, int ldb,
                                                       float* __restrict__ Co,
                                                       const float* __restrict__ bias,
                                                       int M, int N, int K)
{
    __shared__ float As[BK][BM];
    __shared__ float Bs[BK][BN];
    const int tid = threadIdx.x;
    const int m0 = blockIdx.y * BM;
    const int n0 = blockIdx.x * BN;
    const int tcols = BN / TN;
    const int tr = tid / tcols, tc = tid % tcols;

    float acc[TM][TN];
    #pragma unroll
    for (int i = 0; i < TM; i++)
        #pragma unroll
        for (int j = 0; j < TN; j++) acc[i][j] = 0.f;

    for (int k0 = 0; k0 < K; k0 += BK) {
        for (int i = tid * 4; i < BM * BK; i += 256 * 4) {
            int r = i / BK, c = i % BK;
            float4 v = *reinterpret_cast<const float4*>(&A[(size_t)(m0 + r) * lda + k0 + c]);
            As[c + 0][r] = v.x; As[c + 1][r] = v.y;
            As[c + 2][r] = v.z; As[c + 3][r] = v.w;
        }
        for (int i = tid * 4; i < BK * BN; i += 256 * 4) {
            int r = i / BN, c = i % BN;
            *reinterpret_cast<float4*>(&Bs[r][c]) =
                *reinterpret_cast<const float4*>(&B[(size_t)(k0 + r) * ldb + n0 + c]);
        }
        __syncthreads();
        #pragma unroll
        for (int kk = 0; kk < BK; ++kk) {
            float ra[TM], rb[TN];
            #pragma unroll
            for (int i = 0; i < TM; i += 4) {
                float4 v = *reinterpret_cast<const float4*>(&As[kk][tr * TM + i]);
                ra[i] = v.x; ra[i + 1] = v.y; ra[i + 2] = v.z; ra[i + 3] = v.w;
            }
            #pragma unroll
            for (int j = 0; j < TN; j += 4) {
                float4 v = *reinterpret_cast<const float4*>(&Bs[kk][tc * TN + j]);
                rb[j] = v.x; rb[j + 1] = v.y; rb[j + 2] = v.z; rb[j + 3] = v.w;
            }
            #pragma unroll
            for (int i = 0; i < TM; i++)
                #pragma unroll
                for (int j = 0; j < TN; j++)
                    acc[i][j] = fmaf(ra[i], rb[j], acc[i][j]);
        }
        __syncthreads();
    }
    #pragma unroll
    for (int i = 0; i < TM; i++) {
        int m = m0 + tr * TM + i;
        #pragma unroll
        for (int j = 0; j < TN; j++) {
            int n = n0 + tc * TN + j;
            float v = acc[i][j] + bias[n];
            Co[(size_t)m * N + n] = (v > 20.f) ? v : log1pf(__expf(v));
        }
    }
}

// ---------------- chunked selective scan ----------------
// Group index G in [0, NCH*BB*DI): d = G & 1023, b = (G>>10)&1, chunk = G>>11.
// 16 lanes (n) per group, 16 groups per 256-thread block.

// Pass A: local scan from h=0; emit P = prod(dA), H = local final h.
__global__ __launch_bounds__(256) void scan_partial_kernel(const float* __restrict__ dt,
                                                           const float* __restrict__ xc,
                                                           const float* __restrict__ proj,
                                                           const float* __restrict__ A_log,
                                                           float* __restrict__ gP,
                                                           float* __restrict__ gH)
{
    int tid = threadIdx.x;
    int n = tid & 15;
    int G = blockIdx.x * 16 + (tid >> 4);
    int d = G & (DI - 1), b = (G >> 10) & 1, chunk = G >> 11;
    float a = -__expf(A_log[d * NS + n]);
    float P = 1.f, h = 0.f;
    int t0 = b * LL + chunk * CLEN;
    for (int l = 0; l < CLEN; l += 4) {
        float dtv[4], xcv[4], Bv[4];
        #pragma unroll
        for (int u = 0; u < 4; u++) {
            int t = t0 + l + u;
            dtv[u] = dt[(size_t)t * DI + d];
            xcv[u] = xc[(size_t)t * DI + d];
            Bv[u]  = proj[t * 64 + DTR + n];
        }
        #pragma unroll
        for (int u = 0; u < 4; u++) {
            float dA = __expf(dtv[u] * a);
            P *= dA;
            h = fmaf(dA, h, dtv[u] * xcv[u] * Bv[u]);
        }
    }
    gP[G * NS + n] = P;
    gH[G * NS + n] = h;
}

// Pass B: serial combine over chunks -> h0 entering each chunk.
__global__ __launch_bounds__(256) void scan_combine_kernel(const float* __restrict__ gP,
                                                           const float* __restrict__ gH,
                                                           float* __restrict__ gh0)
{
    int id = blockIdx.x * 256 + threadIdx.x;     // over BB*DI*NS
    int n = id & 15, d = (id >> 4) & (DI - 1), b = id >> 14;
    float h0 = 0.f;
    #pragma unroll
    for (int c = 0; c < NCH; c++) {
        int G = (c << 11) | (b << 10) | d;
        gh0[G * NS + n] = h0;
        h0 = fmaf(gP[G * NS + n], h0, gH[G * NS + n]);
    }
}

// Pass C: rerun recurrence seeded with h0; emit gated bf16 y.
__global__ __launch_bounds__(256) void scan_final_kernel(const float* __restrict__ dt,
                                                         const float* __restrict__ xc,
                                                         const float* __restrict__ proj,
                                                         const float* __restrict__ xz,
                                                         const float* __restrict__ A_log,
                                                         const float* __restrict__ D_param,
                                                         const float* __restrict__ gh0,
                                                         __nv_bfloat16* __restrict__ y)
{
    int tid = threadIdx.x;
    int n = tid & 15;
    int G = blockIdx.x * 16 + (tid >> 4);
    int d = G & (DI - 1), b = (G >> 10) & 1, chunk = G >> 11;
    float a = -__expf(A_log[d * NS + n]);
    float Dp = D_param[d];
    float h = gh0[G * NS + n];
    int t0 = b * LL + chunk * CLEN;
    for (int l = 0; l < CLEN; l += 4) {
        float dtv[4], xcv[4], Bv[4], Cv[4], zv[4];
        #pragma unroll
        for (int u = 0; u < 4; u++) {
            int t = t0 + l + u;
            dtv[u] = dt[(size_t)t * DI + d];
            xcv[u] = xc[(size_t)t * DI + d];
            Bv[u]  = proj[t * 64 + DTR + n];
            Cv[u]  = proj[t * 64 + DTR + NS + n];
            zv[u]  = xz[(size_t)t * (2 * DI) + DI + d];
        }
        #pragma unroll
        for (int u = 0; u < 4; u++) {
            float dA = __expf(dtv[u] * a);
            h = fmaf(dA, h, dtv[u] * xcv[u] * Bv[u]);
            float p = h * Cv[u];
            p += __shfl_xor_sync(0xffffffffu, p, 8);
            p += __shfl_xor_sync(0xffffffffu, p, 4);
            p += __shfl_xor_sync(0xffffffffu, p, 2);
            p += __shfl_xor_sync(0xffffffffu, p, 1);
            if (n == 0) {
                int t = t0 + l + u;
                float sg = 1.f / (1.f + __expf(-zv[u]));
                y[(size_t)t * DI + d] =
                    __float2bfloat16((p + Dp * xcv[u]) * (zv[u] * sg));
            }
        }
    }
}

// ---------------- launch ----------------
extern "C" void kernel_launch(void* const* d_in, const int* in_sizes, int n_in,
                              void* d_out, int out_size)
{
    const float* x       = (const float*)d_in[0];
    const float* gamma   = (const float*)d_in[1];
    const float* beta    = (const float*)d_in[2];
    const float* W_in    = (const float*)d_in[3];
    const float* conv_w  = (const float*)d_in[4];
    const float* conv_b  = (const float*)d_in[5];
    const float* W_x     = (const float*)d_in[6];
    const float* W_dt    = (const float*)d_in[7];
    const float* b_dt    = (const float*)d_in[8];
    const float* A_log   = (const float*)d_in[9];
    const float* D_param = (const float*)d_in[10];
    const float* W_out   = (const float*)d_in[11];
    float* out = (float*)d_out;

    __nv_bfloat16 *p_xnT, *p_ybf, *p_Win, *p_Wout;
    float *p_xz, *p_xc, *p_proj, *p_dt, *p_P, *p_H, *p_h0;
    cudaGetSymbolAddress((void**)&p_xnT, g_xnT);
    cudaGetSymbolAddress((void**)&p_xz,  g_xz);
    cudaGetSymbolAddress((void**)&p_xc,  g_xc);
    cudaGetSymbolAddress((void**)&p_proj,g_proj);
    cudaGetSymbolAddress((void**)&p_dt,  g_dt);
    cudaGetSymbolAddress((void**)&p_ybf, g_ybf);
    cudaGetSymbolAddress((void**)&p_Win, g_Win_bf);
    cudaGetSymbolAddress((void**)&p_Wout,g_Wout_bf);
    cudaGetSymbolAddress((void**)&p_P,   g_P);
    cudaGetSymbolAddress((void**)&p_H,   g_H);
    cudaGetSymbolAddress((void**)&p_h0,  g_h0);

    f2bf_kernel<<<(CC * 2 * DI) / 1024, 256>>>(W_in,  p_Win,  CC * 2 * DI);
    f2bf_kernel<<<(DI * CC) / 1024, 256>>>(W_out, p_Wout, DI * CC);

    ln_kernel<<<BB * (LL / 32), 1024>>>(x, gamma, beta, p_xnT);

    {   // in-proj (2048x512)@(512x2048)
        dim3 grid((2 * DI) / 128, NTOK / 128);
        mma_gemm_acol<<<grid, 256>>>(p_xnT, p_Win, p_xz, NTOK, 2 * DI, CC);
    }

    conv_silu_kernel<<<NTOK * DI / 1024, 256>>>(p_xz, conv_w, conv_b, p_xc);

    xproj_kernel<<<NTOK / 8, 256>>>(p_xc, W_x, p_proj);

    {   // dt GEMM + softplus
        dim3 grid(DI / 128, NTOK / 128);
        sgemm_dt_kernel<128, 128, 8, 8, 8><<<grid, 256>>>(
            p_proj, 64, W_dt, DI, p_dt, b_dt, NTOK, DI, DTR);
    }

    // chunked scan: partial -> combine -> final
    scan_partial_kernel<<<NCH * BB * DI / 16, 256>>>(p_dt, p_xc, p_proj, A_log, p_P, p_H);
    scan_combine_kernel<<<BB * DI * NS / 256, 256>>>(p_P, p_H, p_h0);
    scan_final_kernel<<<NCH * BB * DI / 16, 256>>>(p_dt, p_xc, p_proj, p_xz,
                                                   A_log, D_param, p_h0, p_ybf);

    {   // out-proj (2048x1024)@(1024x512) + residual
        dim3 grid(CC / 64, NTOK / 128);
        mma_gemm_arow_res<<<grid, 256>>>(p_ybf, p_Wout, out, x, NTOK, CC, DI);
    }
}

// round 11
// speedup vs baseline: 6.5076x; 1.0073x over previous
#include <cuda_runtime.h>
#include <cuda_bf16.h>
#include <mma.h>

using namespace nvcuda;

#define BB 2
#define CC 512
#define LL 1024
#define DI 1024
#define NS 16
#define DTR 32
#define NTOK (BB*LL)
#define NCH 16
#define CLEN 64

// ---------------- scratch ----------------
__device__ __nv_bfloat16 g_xnT[CC * NTOK];
__device__ float         g_xz[NTOK * 2 * DI];
__device__ float         g_xc[NTOK * DI];
__device__ float         g_proj[NTOK * 64];
__device__ float         g_dt[NTOK * DI];
__device__ __nv_bfloat16 g_ybf[NTOK * DI];
__device__ __nv_bfloat16 g_Win_bf[CC * 2 * DI];
__device__ __nv_bfloat16 g_Wout_bf[DI * CC];
__device__ float         g_P [BB * DI * NCH * NS];
__device__ float         g_H [BB * DI * NCH * NS];
__device__ float         g_h0[BB * DI * NCH * NS];

// ---------------- cp.async helpers ----------------
__device__ __forceinline__ void cp_async16(unsigned dst, const void* src) {
    asm volatile("cp.async.cg.shared.global [%0], [%1], 16;\n" :: "r"(dst), "l"(src));
}
__device__ __forceinline__ void cp_commit() {
    asm volatile("cp.async.commit_group;\n" ::: "memory");
}
__device__ __forceinline__ void cp_wait1() {
    asm volatile("cp.async.wait_group 1;\n" ::: "memory");
}

// ---------------- fp32 -> bf16 ----------------
__global__ __launch_bounds__(256) void f2bf_kernel(const float* __restrict__ in,
                                                   __nv_bfloat16* __restrict__ out, int n)
{
    int i = (blockIdx.x * 256 + threadIdx.x) * 4;
    if (i < n) {
        float4 v = *reinterpret_cast<const float4*>(&in[i]);
        out[i + 0] = __float2bfloat16(v.x);
        out[i + 1] = __float2bfloat16(v.y);
        out[i + 2] = __float2bfloat16(v.z);
        out[i + 3] = __float2bfloat16(v.w);
    }
}

// ---------------- LayerNorm ----------------
__global__ __launch_bounds__(1024) void ln_kernel(const float* __restrict__ x,
                                                  const float* __restrict__ gamma,
                                                  const float* __restrict__ beta,
                                                  __nv_bfloat16* __restrict__ xnT)
{
    int bx = blockIdx.x;
    int b  = bx >> 5;
    int l0 = (bx & 31) * 32;
    int tid  = threadIdx.x;
    int lane = tid & 31;
    int cg   = tid >> 5;

    const float* xb = x + (size_t)b * CC * LL + l0 + lane;
    float vv[16];
    float s = 0.f, q = 0.f;
    #pragma unroll
    for (int i = 0; i < 16; i++) {
        int c = cg * 16 + i;
        float v = xb[(size_t)c * LL];
        vv[i] = v;
        s += v; q += v * v;
    }
    __shared__ float red_s[32][32], red_q[32][32];
    red_s[cg][lane] = s; red_q[cg][lane] = q;
    __syncthreads();
    float ts = 0.f, tq = 0.f;
    #pragma unroll
    for (int g = 0; g < 32; g++) { ts += red_s[g][lane]; tq += red_q[g][lane]; }
    float mu  = ts * (1.f / CC);
    float var = tq * (1.f / CC) - mu * mu;
    float rs  = rsqrtf(var + 1e-5f);

    int t = b * LL + l0 + lane;
    #pragma unroll
    for (int i = 0; i < 16; i++) {
        int c = cg * 16 + i;
        float v = (vv[i] - mu) * rs * gamma[c] + beta[c];
        xnT[(size_t)c * NTOK + t] = __float2bfloat16(v);
    }
}

// ---------------- in-proj wmma, cp.async 3-stage pipeline ----------------
// BM=BN=128, BK=32, 3 stages dynamic smem (52224 B), one sync per iter.
__global__ __launch_bounds__(256) void mma_gemm_acol(const __nv_bfloat16* __restrict__ AT,
                                                     const __nv_bfloat16* __restrict__ B,
                                                     float* __restrict__ C,
                                                     int M, int N, int K)
{
    constexpr int BM = 128, BN = 128, BK = 32;
    constexpr int LDA = BM + 8, LDB = BN + 8;     // 136
    constexpr int ABYTES = BK * LDA * 2;          // 8704
    constexpr int STAGE  = ABYTES * 2;            // 17408 (A+B)
    extern __shared__ __align__(16) unsigned char dynsm[];

    const int tid = threadIdx.x;
    const int wid = tid >> 5;
    const int m0 = blockIdx.y * BM;
    const int n0 = blockIdx.x * BN;
    const int wm = wid & 1, wn = wid >> 1;
    constexpr int WTM = 64, WTN = 32;
    constexpr int FM = 4, FN = 2;

    const int ar0 = tid >> 4, ac = (tid & 15) * 8;
    const int ar1 = ar0 + 16;
    const int kt = K / BK;                        // 16

    wmma::fragment<wmma::accumulator, 16, 16, 16, float> acc[FM][FN];
    #pragma unroll
    for (int i = 0; i < FM; i++)
        #pragma unroll
        for (int j = 0; j < FN; j++) wmma::fill_fragment(acc[i][j], 0.f);

    // per-stage smem pointers
    auto AsP = [&](int s) { return reinterpret_cast<__nv_bfloat16*>(dynsm + s * STAGE); };
    auto BsP = [&](int s) { return reinterpret_cast<__nv_bfloat16*>(dynsm + s * STAGE + ABYTES); };

    // issue one stage's loads (4 x 16B per thread)
    auto issue = [&](int s, int k0) {
        __nv_bfloat16* As = AsP(s);
        __nv_bfloat16* Bs = BsP(s);
        cp_async16((unsigned)__cvta_generic_to_shared(&As[ar0 * LDA + ac]),
                   &AT[(size_t)(k0 + ar0) * M + m0 + ac]);
        cp_async16((unsigned)__cvta_generic_to_shared(&As[ar1 * LDA + ac]),
                   &AT[(size_t)(k0 + ar1) * M + m0 + ac]);
        cp_async16((unsigned)__cvta_generic_to_shared(&Bs[ar0 * LDB + ac]),
                   &B[(size_t)(k0 + ar0) * N + n0 + ac]);
        cp_async16((unsigned)__cvta_generic_to_shared(&Bs[ar1 * LDB + ac]),
                   &B[(size_t)(k0 + ar1) * N + n0 + ac]);
    };

    issue(0, 0);         cp_commit();
    issue(1, BK);        cp_commit();

    for (int it = 0; it < kt; ++it) {
        cp_wait1();
        __syncthreads();
        int sb = it % 3;
        __nv_bfloat16* As = AsP(sb);
        __nv_bfloat16* Bs = BsP(sb);
        #pragma unroll
        for (int kk = 0; kk < BK; kk += 16) {
            wmma::fragment<wmma::matrix_a, 16, 16, 16, __nv_bfloat16, wmma::col_major> af[FM];
            wmma::fragment<wmma::matrix_b, 16, 16, 16, __nv_bfloat16, wmma::row_major> bf[FN];
            #pragma unroll
            for (int i = 0; i < FM; i++)
                wmma::load_matrix_sync(af[i], &As[kk * LDA + wm * WTM + i * 16], LDA);
            #pragma unroll
            for (int j = 0; j < FN; j++)
                wmma::load_matrix_sync(bf[j], &Bs[kk * LDB + wn * WTN + j * 16], LDB);
            #pragma unroll
            for (int i = 0; i < FM; i++)
                #pragma unroll
                for (int j = 0; j < FN; j++)
                    wmma::mma_sync(acc[i][j], af[i], bf[j], acc[i][j]);
        }
        if (it + 2 < kt) issue((it + 2) % 3, (it + 2) * BK);
        cp_commit();
    }
    #pragma unroll
    for (int i = 0; i < FM; i++)
        #pragma unroll
        for (int j = 0; j < FN; j++)
            wmma::store_matrix_sync(&C[(size_t)(m0 + wm * WTM + i * 16) * N + n0 + wn * WTN + j * 16],
                                    acc[i][j], N, wmma::mem_row_major);
}

// ---------------- out-proj wmma + fused transposed residual ----------------
__global__ __launch_bounds__(256) void mma_gemm_arow_res(const __nv_bfloat16* __restrict__ A,
                                                         const __nv_bfloat16* __restrict__ B,
                                                         float* __restrict__ out,
                                                         const float* __restrict__ x,
                                                         int M, int N, int K)
{
    constexpr int BM = 128, BN = 64, BK = 32;
    constexpr int LDA = BK + 8;
    constexpr int LDB = BN + 8;
    constexpr int LDC = BM + 4;
    constexpr int ASZ = BM * LDA * 2;
    constexpr int BSZ = BK * LDB * 2;
    constexpr int CSZ = BN * LDC * 4;
    constexpr int SMEM = (ASZ + BSZ) > CSZ ? (ASZ + BSZ) : CSZ;
    __shared__ __align__(16) unsigned char sraw[SMEM];
    __nv_bfloat16* As = reinterpret_cast<__nv_bfloat16*>(sraw);
    __nv_bfloat16* Bs = reinterpret_cast<__nv_bfloat16*>(sraw + ASZ);
    float* Cs = reinterpret_cast<float*>(sraw);

    const int tid = threadIdx.x;
    const int wid = tid >> 5;
    const int m0 = blockIdx.y * BM;
    const int n0 = blockIdx.x * BN;
    const int wm = wid & 3, wn = wid >> 2;
    constexpr int WTM = 32, WTN = 32;
    constexpr int FM = 2, FN = 2;

    const int ar0 = tid >> 2, aco = (tid & 3) * 8;
    const int ar1 = ar0 + 64;
    const int br = tid >> 3, bc = (tid & 7) * 8;

    wmma::fragment<wmma::accumulator, 16, 16, 16, float> acc[FM][FN];
    #pragma unroll
    for (int i = 0; i < FM; i++)
        #pragma unroll
        for (int j = 0; j < FN; j++) wmma::fill_fragment(acc[i][j], 0.f);

    uint4 pa0 = *reinterpret_cast<const uint4*>(&A[(size_t)(m0 + ar0) * K + aco]);
    uint4 pa1 = *reinterpret_cast<const uint4*>(&A[(size_t)(m0 + ar1) * K + aco]);
    uint4 pb  = *reinterpret_cast<const uint4*>(&B[(size_t)br * N + n0 + bc]);
    *reinterpret_cast<uint4*>(&As[ar0 * LDA + aco]) = pa0;
    *reinterpret_cast<uint4*>(&As[ar1 * LDA + aco]) = pa1;
    *reinterpret_cast<uint4*>(&Bs[br * LDB + bc])   = pb;
    __syncthreads();

    for (int k0 = 0; k0 < K; k0 += BK) {
        int kn = k0 + BK;
        if (kn < K) {
            pa0 = *reinterpret_cast<const uint4*>(&A[(size_t)(m0 + ar0) * K + kn + aco]);
            pa1 = *reinterpret_cast<const uint4*>(&A[(size_t)(m0 + ar1) * K + kn + aco]);
            pb  = *reinterpret_cast<const uint4*>(&B[(size_t)(kn + br) * N + n0 + bc]);
        }
        #pragma unroll
        for (int kk = 0; kk < BK; kk += 16) {
            wmma::fragment<wmma::matrix_a, 16, 16, 16, __nv_bfloat16, wmma::row_major> af[FM];
            wmma::fragment<wmma::matrix_b, 16, 16, 16, __nv_bfloat16, wmma::row_major> bf[FN];
            #pragma unroll
            for (int i = 0; i < FM; i++)
                wmma::load_matrix_sync(af[i], &As[(wm * WTM + i * 16) * LDA + kk], LDA);
            #pragma unroll
            for (int j = 0; j < FN; j++)
                wmma::load_matrix_sync(bf[j], &Bs[kk * LDB + wn * WTN + j * 16], LDB);
            #pragma unroll
            for (int i = 0; i < FM; i++)
                #pragma unroll
                for (int j = 0; j < FN; j++)
                    wmma::mma_sync(acc[i][j], af[i], bf[j], acc[i][j]);
        }
        __syncthreads();
        if (kn < K) {
            *reinterpret_cast<uint4*>(&As[ar0 * LDA + aco]) = pa0;
            *reinterpret_cast<uint4*>(&As[ar1 * LDA + aco]) = pa1;
            *reinterpret_cast<uint4*>(&Bs[br * LDB + bc])   = pb;
            __syncthreads();
        }
    }

    #pragma unroll
    for (int i = 0; i < FM; i++)
        #pragma unroll
        for (int j = 0; j < FN; j++)
            wmma::store_matrix_sync(&Cs[(wn * WTN + j * 16) * LDC + wm * WTM + i * 16],
                                    acc[i][j], LDC, wmma::mem_col_major);
    __syncthreads();

    int b   = m0 >> 10;
    int l0b = m0 & (LL - 1);
    #pragma unroll
    for (int idx = tid; idx < BM * BN; idx += 256) {
        int n = idx / BM;
        int m = idx % BM;
        size_t gi = ((size_t)(b * CC + n0 + n)) * LL + l0b + m;
        out[gi] = Cs[n * LDC + m] + x[gi];
    }
}

// ---------------- fused conv+SiLU+x-proj: 8 tokens/block ----------------
// dynamic smem: sx[11*1024] | sc[8*1024] | ps[4*8*64]  (86016 B)
__global__ __launch_bounds__(256) void convxproj_kernel(const float* __restrict__ xz,
                                                        const float* __restrict__ conv_w,
                                                        const float* __restrict__ conv_b,
                                                        const float* __restrict__ Wx,
                                                        float* __restrict__ xc,
                                                        float* __restrict__ proj)
{
    extern __shared__ __align__(16) float dynf[];
    float* sx = dynf;                  // 11 rows x 1024
    float* sc = dynf + 11 * 1024;      // 8 rows x 1024
    float* ps = sc + 8 * 1024;         // [4][8][64]

    int tid = threadIdx.x;
    int t0 = blockIdx.x * 8;
    int l0 = t0 & (LL - 1);

    // load xi rows t0-3 .. t0+7 (zero-pad before sequence start)
    #pragma unroll
    for (int i = tid * 4; i < 11 * 1024; i += 256 * 4) {
        int row = i >> 10;
        int col = i & 1023;
        float4 v = make_float4(0.f, 0.f, 0.f, 0.f);
        if (l0 - 3 + row >= 0)
            v = *reinterpret_cast<const float4*>(&xz[(size_t)(t0 - 3 + row) * (2 * DI) + col]);
        *reinterpret_cast<float4*>(&sx[i]) = v;
    }
    __syncthreads();

    // conv + silu -> sc + global xc
    #pragma unroll
    for (int j = 0; j < 32; j++) {
        int o = j * 256 + tid;
        int tok = o >> 10, d = o & 1023;
        float v = conv_b[d];
        #pragma unroll
        for (int k = 0; k < 4; k++)
            v = fmaf(conv_w[d * 4 + k], sx[(tok + k) * 1024 + d], v);
        v *= 1.f / (1.f + __expf(-v));
        sc[tok * 1024 + d] = v;
        xc[(size_t)(t0 + tok) * DI + d] = v;
    }
    __syncthreads();

    // x-proj from sc
    int col = tid & 63, g = tid >> 6;
    int kbase = g * 256;
    float acc[8];
    #pragma unroll
    for (int i = 0; i < 8; i++) acc[i] = 0.f;
    #pragma unroll 4
    for (int k = 0; k < 256; k++) {
        float bv = __ldg(&Wx[(kbase + k) * 64 + col]);
        #pragma unroll
        for (int tok = 0; tok < 8; tok++)
            acc[tok] = fmaf(sc[tok * 1024 + kbase + k], bv, acc[tok]);
    }
    #pragma unroll
    for (int tok = 0; tok < 8; tok++) ps[(g * 8 + tok) * 64 + col] = acc[tok];
    __syncthreads();
    #pragma unroll
    for (int j2 = 0; j2 < 2; j2++) {
        int tok = (tid >> 6) + 4 * j2;
        float r = ps[(0 * 8 + tok) * 64 + col] + ps[(1 * 8 + tok) * 64 + col]
                + ps[(2 * 8 + tok) * 64 + col] + ps[(3 * 8 + tok) * 64 + col];
        proj[(size_t)(t0 + tok) * 64 + col] = r;
    }
}

// ---------------- dt GEMM + softplus ----------------
template<int BM, int BN, int BK, int TM, int TN>
__global__ __launch_bounds__(256) void sgemm_dt_kernel(const float* __restrict__ A, int lda,
                                                       const float* __restrict__ B, int ldb,
                                                       float* __restrict__ Co,
                                                       const float* __restrict__ bias,
                                                       int M, int N, int K)
{
    __shared__ float As[BK][BM];
    __shared__ float Bs[BK][BN];
    const int tid = threadIdx.x;
    const int m0 = blockIdx.y * BM;
    const int n0 = blockIdx.x * BN;
    const int tcols = BN / TN;
    const int tr = tid / tcols, tc = tid % tcols;

    float acc[TM][TN];
    #pragma unroll
    for (int i = 0; i < TM; i++)
        #pragma unroll
        for (int j = 0; j < TN; j++) acc[i][j] = 0.f;

    for (int k0 = 0; k0 < K; k0 += BK) {
        for (int i = tid * 4; i < BM * BK; i += 256 * 4) {
            int r = i / BK, c = i % BK;
            float4 v = *reinterpret_cast<const float4*>(&A[(size_t)(m0 + r) * lda + k0 + c]);
            As[c + 0][r] = v.x; As[c + 1][r] = v.y;
            As[c + 2][r] = v.z; As[c + 3][r] = v.w;
        }
        for (int i = tid * 4; i < BK * BN; i += 256 * 4) {
            int r = i / BN, c = i % BN;
            *reinterpret_cast<float4*>(&Bs[r][c]) =
                *reinterpret_cast<const float4*>(&B[(size_t)(k0 + r) * ldb + n0 + c]);
        }
        __syncthreads();
        #pragma unroll
        for (int kk = 0; kk < BK; ++kk) {
            float ra[TM], rb[TN];
            #pragma unroll
            for (int i = 0; i < TM; i += 4) {
                float4 v = *reinterpret_cast<const float4*>(&As[kk][tr * TM + i]);
                ra[i] = v.x; ra[i + 1] = v.y; ra[i + 2] = v.z; ra[i + 3] = v.w;
            }
            #pragma unroll
            for (int j = 0; j < TN; j += 4) {
                float4 v = *reinterpret_cast<const float4*>(&Bs[kk][tc * TN + j]);
                rb[j] = v.x; rb[j + 1] = v.y; rb[j + 2] = v.z; rb[j + 3] = v.w;
            }
            #pragma unroll
            for (int i = 0; i < TM; i++)
                #pragma unroll
                for (int j = 0; j < TN; j++)
                    acc[i][j] = fmaf(ra[i], rb[j], acc[i][j]);
        }
        __syncthreads();
    }
    #pragma unroll
    for (int i = 0; i < TM; i++) {
        int m = m0 + tr * TM + i;
        #pragma unroll
        for (int j = 0; j < TN; j++) {
            int n = n0 + tc * TN + j;
            float v = acc[i][j] + bias[n];
            Co[(size_t)m * N + n] = (v > 20.f) ? v : log1pf(__expf(v));
        }
    }
}

// ---------------- chunked selective scan ----------------
__global__ __launch_bounds__(256) void scan_partial_kernel(const float* __restrict__ dt,
                                                           const float* __restrict__ xc,
                                                           const float* __restrict__ proj,
                                                           const float* __restrict__ A_log,
                                                           float* __restrict__ gP,
                                                           float* __restrict__ gH)
{
    int tid = threadIdx.x;
    int n = tid & 15;
    int G = blockIdx.x * 16 + (tid >> 4);
    int d = G & (DI - 1), b = (G >> 10) & 1, chunk = G >> 11;
    float a = -__expf(A_log[d * NS + n]);
    float P = 1.f, h = 0.f;
    int t0 = b * LL + chunk * CLEN;
    for (int l = 0; l < CLEN; l += 4) {
        float dtv[4], xcv[4], Bv[4];
        #pragma unroll
        for (int u = 0; u < 4; u++) {
            int t = t0 + l + u;
            dtv[u] = dt[(size_t)t * DI + d];
            xcv[u] = xc[(size_t)t * DI + d];
            Bv[u]  = proj[t * 64 + DTR + n];
        }
        #pragma unroll
        for (int u = 0; u < 4; u++) {
            float dA = __expf(dtv[u] * a);
            P *= dA;
            h = fmaf(dA, h, dtv[u] * xcv[u] * Bv[u]);
        }
    }
    gP[G * NS + n] = P;
    gH[G * NS + n] = h;
}

__global__ __launch_bounds__(256) void scan_combine_kernel(const float* __restrict__ gP,
                                                           const float* __restrict__ gH,
                                                           float* __restrict__ gh0)
{
    int id = blockIdx.x * 256 + threadIdx.x;
    int n = id & 15, d = (id >> 4) & (DI - 1), b = id >> 14;
    float h0 = 0.f;
    #pragma unroll
    for (int c = 0; c < NCH; c++) {
        int G = (c << 11) | (b << 10) | d;
        gh0[G * NS + n] = h0;
        h0 = fmaf(gP[G * NS + n], h0, gH[G * NS + n]);
    }
}

__global__ __launch_bounds__(256) void scan_final_kernel(const float* __restrict__ dt,
                                                         const float* __restrict__ xc,
                                                         const float* __restrict__ proj,
                                                         const float* __restrict__ xz,
                                                         const float* __restrict__ A_log,
                                                         const float* __restrict__ D_param,
                                                         const float* __restrict__ gh0,
                                                         __nv_bfloat16* __restrict__ y)
{
    int tid = threadIdx.x;
    int n = tid & 15;
    int G = blockIdx.x * 16 + (tid >> 4);
    int d = G & (DI - 1), b = (G >> 10) & 1, chunk = G >> 11;
    float a = -__expf(A_log[d * NS + n]);
    float Dp = D_param[d];
    float h = gh0[G * NS + n];
    int t0 = b * LL + chunk * CLEN;
    for (int l = 0; l < CLEN; l += 4) {
        float dtv[4], xcv[4], Bv[4], Cv[4], zv[4];
        #pragma unroll
        for (int u = 0; u < 4; u++) {
            int t = t0 + l + u;
            dtv[u] = dt[(size_t)t * DI + d];
            xcv[u] = xc[(size_t)t * DI + d];
            Bv[u]  = proj[t * 64 + DTR + n];
            Cv[u]  = proj[t * 64 + DTR + NS + n];
            zv[u]  = xz[(size_t)t * (2 * DI) + DI + d];
        }
        #pragma unroll
        for (int u = 0; u < 4; u++) {
            float dA = __expf(dtv[u] * a);
            h = fmaf(dA, h, dtv[u] * xcv[u] * Bv[u]);
            float p = h * Cv[u];
            p += __shfl_xor_sync(0xffffffffu, p, 8);
            p += __shfl_xor_sync(0xffffffffu, p, 4);
            p += __shfl_xor_sync(0xffffffffu, p, 2);
            p += __shfl_xor_sync(0xffffffffu, p, 1);
            if (n == 0) {
                int t = t0 + l + u;
                float sg = 1.f / (1.f + __expf(-zv[u]));
                y[(size_t)t * DI + d] =
                    __float2bfloat16((p + Dp * xcv[u]) * (zv[u] * sg));
            }
        }
    }
}

// ---------------- launch ----------------
extern "C" void kernel_launch(void* const* d_in, const int* in_sizes, int n_in,
                              void* d_out, int out_size)
{
    const float* x       = (const float*)d_in[0];
    const float* gamma   = (const float*)d_in[1];
    const float* beta    = (const float*)d_in[2];
    const float* W_in    = (const float*)d_in[3];
    const float* conv_w  = (const float*)d_in[4];
    const float* conv_b  = (const float*)d_in[5];
    const float* W_x     = (const float*)d_in[6];
    const float* W_dt    = (const float*)d_in[7];
    const float* b_dt    = (const float*)d_in[8];
    const float* A_log   = (const float*)d_in[9];
    const float* D_param = (const float*)d_in[10];
    const float* W_out   = (const float*)d_in[11];
    float* out = (float*)d_out;

    __nv_bfloat16 *p_xnT, *p_ybf, *p_Win, *p_Wout;
    float *p_xz, *p_xc, *p_proj, *p_dt, *p_P, *p_H, *p_h0;
    cudaGetSymbolAddress((void**)&p_xnT, g_xnT);
    cudaGetSymbolAddress((void**)&p_xz,  g_xz);
    cudaGetSymbolAddress((void**)&p_xc,  g_xc);
    cudaGetSymbolAddress((void**)&p_proj,g_proj);
    cudaGetSymbolAddress((void**)&p_dt,  g_dt);
    cudaGetSymbolAddress((void**)&p_ybf, g_ybf);
    cudaGetSymbolAddress((void**)&p_Win, g_Win_bf);
    cudaGetSymbolAddress((void**)&p_Wout,g_Wout_bf);
    cudaGetSymbolAddress((void**)&p_P,   g_P);
    cudaGetSymbolAddress((void**)&p_H,   g_H);
    cudaGetSymbolAddress((void**)&p_h0,  g_h0);

    constexpr int INPROJ_SMEM = 3 * (32 * 136 * 2) * 2;      // 52224
    constexpr int CXP_SMEM    = (11 * 1024 + 8 * 1024 + 4 * 8 * 64) * 4;  // 86016
    cudaFuncSetAttribute(mma_gemm_acol, cudaFuncAttributeMaxDynamicSharedMemorySize, INPROJ_SMEM);
    cudaFuncSetAttribute(convxproj_kernel, cudaFuncAttributeMaxDynamicSharedMemorySize, CXP_SMEM);

    f2bf_kernel<<<(CC * 2 * DI) / 1024, 256>>>(W_in,  p_Win,  CC * 2 * DI);
    f2bf_kernel<<<(DI * CC) / 1024, 256>>>(W_out, p_Wout, DI * CC);

    ln_kernel<<<BB * (LL / 32), 1024>>>(x, gamma, beta, p_xnT);

    {   // in-proj (2048x512)@(512x2048), cp.async pipelined
        dim3 grid((2 * DI) / 128, NTOK / 128);
        mma_gemm_acol<<<grid, 256, INPROJ_SMEM>>>(p_xnT, p_Win, p_xz, NTOK, 2 * DI, CC);
    }

    // fused conv+silu+x-proj
    convxproj_kernel<<<NTOK / 8, 256, CXP_SMEM>>>(p_xz, conv_w, conv_b, W_x, p_xc, p_proj);

    {   // dt GEMM + softplus
        dim3 grid(DI / 128, NTOK / 128);
        sgemm_dt_kernel<128, 128, 8, 8, 8><<<grid, 256>>>(
            p_proj, 64, W_dt, DI, p_dt, b_dt, NTOK, DI, DTR);
    }

    // chunked scan
    scan_partial_kernel<<<NCH * BB * DI / 16, 256>>>(p_dt, p_xc, p_proj, A_log, p_P, p_H);
    scan_combine_kernel<<<BB * DI * NS / 256, 256>>>(p_P, p_H, p_h0);
    scan_final_kernel<<<NCH * BB * DI / 16, 256>>>(p_dt, p_xc, p_proj, p_xz,
                                                   A_log, D_param, p_h0, p_ybf);

    {   // out-proj + residual
        dim3 grid(CC / 64, NTOK / 128);
        mma_gemm_arow_res<<<grid, 256>>>(p_ybf, p_Wout, out, x, NTOK, CC, DI);
    }
}

// round 12
// speedup vs baseline: 6.7807x; 1.0420x over previous
#include <cuda_runtime.h>
#include <cuda_bf16.h>
#include <mma.h>

using namespace nvcuda;

#define BB 2
#define CC 512
#define LL 1024
#define DI 1024
#define NS 16
#define DTR 32
#define NTOK (BB*LL)
#define NCH 16
#define CLEN 64

// ---------------- scratch ----------------
__device__ __nv_bfloat16 g_xnT[CC * NTOK];
__device__ float         g_xz[NTOK * 2 * DI];
__device__ float         g_xc[NTOK * DI];
__device__ float         g_proj[NTOK * 64];
__device__ float         g_dt[NTOK * DI];
__device__ __nv_bfloat16 g_ybf[NTOK * DI];
__device__ __nv_bfloat16 g_Win_bf[CC * 2 * DI];
__device__ __nv_bfloat16 g_Wout_bf[DI * CC];
__device__ float         g_P [BB * DI * NCH * NS];
__device__ float         g_H [BB * DI * NCH * NS];
__device__ float         g_h0[BB * DI * NCH * NS];

// ---------------- cp.async helpers ----------------
__device__ __forceinline__ void cp_async16(unsigned dst, const void* src) {
    asm volatile("cp.async.cg.shared.global [%0], [%1], 16;\n" :: "r"(dst), "l"(src));
}
__device__ __forceinline__ void cp_commit() {
    asm volatile("cp.async.commit_group;\n" ::: "memory");
}
__device__ __forceinline__ void cp_wait1() {
    asm volatile("cp.async.wait_group 1;\n" ::: "memory");
}

// ---------------- fused weight convert (both matrices, one launch) ----------------
__global__ __launch_bounds__(256) void f2bf_dual_kernel(const float* __restrict__ w_in,
                                                        __nv_bfloat16* __restrict__ o_in,
                                                        const float* __restrict__ w_out,
                                                        __nv_bfloat16* __restrict__ o_out)
{
    const int N1 = CC * 2 * DI;           // 1 M elems
    const int N2 = DI * CC;               // 0.5 M elems
    int i = (blockIdx.x * 256 + threadIdx.x) * 4;
    if (i < N1) {
        float4 v = *reinterpret_cast<const float4*>(&w_in[i]);
        o_in[i + 0] = __float2bfloat16(v.x);
        o_in[i + 1] = __float2bfloat16(v.y);
        o_in[i + 2] = __float2bfloat16(v.z);
        o_in[i + 3] = __float2bfloat16(v.w);
    } else if (i - N1 < N2) {
        int j = i - N1;
        float4 v = *reinterpret_cast<const float4*>(&w_out[j]);
        o_out[j + 0] = __float2bfloat16(v.x);
        o_out[j + 1] = __float2bfloat16(v.y);
        o_out[j + 2] = __float2bfloat16(v.z);
        o_out[j + 3] = __float2bfloat16(v.w);
    }
}

// ---------------- LayerNorm ----------------
__global__ __launch_bounds__(1024) void ln_kernel(const float* __restrict__ x,
                                                  const float* __restrict__ gamma,
                                                  const float* __restrict__ beta,
                                                  __nv_bfloat16* __restrict__ xnT)
{
    int bx = blockIdx.x;
    int b  = bx >> 5;
    int l0 = (bx & 31) * 32;
    int tid  = threadIdx.x;
    int lane = tid & 31;
    int cg   = tid >> 5;

    const float* xb = x + (size_t)b * CC * LL + l0 + lane;
    float vv[16];
    float s = 0.f, q = 0.f;
    #pragma unroll
    for (int i = 0; i < 16; i++) {
        int c = cg * 16 + i;
        float v = xb[(size_t)c * LL];
        vv[i] = v;
        s += v; q += v * v;
    }
    __shared__ float red_s[32][32], red_q[32][32];
    red_s[cg][lane] = s; red_q[cg][lane] = q;
    __syncthreads();
    float ts = 0.f, tq = 0.f;
    #pragma unroll
    for (int g = 0; g < 32; g++) { ts += red_s[g][lane]; tq += red_q[g][lane]; }
    float mu  = ts * (1.f / CC);
    float var = tq * (1.f / CC) - mu * mu;
    float rs  = rsqrtf(var + 1e-5f);

    int t = b * LL + l0 + lane;
    #pragma unroll
    for (int i = 0; i < 16; i++) {
        int c = cg * 16 + i;
        float v = (vv[i] - mu) * rs * gamma[c] + beta[c];
        xnT[(size_t)c * NTOK + t] = __float2bfloat16(v);
    }
}

// ---------------- in-proj wmma, cp.async 3-stage, 2 blocks/SM ----------------
__global__ __launch_bounds__(256, 2) void mma_gemm_acol(const __nv_bfloat16* __restrict__ AT,
                                                        const __nv_bfloat16* __restrict__ B,
                                                        float* __restrict__ C,
                                                        int M, int N, int K)
{
    constexpr int BM = 128, BN = 128, BK = 32;
    constexpr int LDA = BM + 8, LDB = BN + 8;
    constexpr int ABYTES = BK * LDA * 2;
    constexpr int STAGE  = ABYTES * 2;
    extern __shared__ __align__(16) unsigned char dynsm[];

    const int tid = threadIdx.x;
    const int wid = tid >> 5;
    const int m0 = blockIdx.y * BM;
    const int n0 = blockIdx.x * BN;
    const int wm = wid & 1, wn = wid >> 1;
    constexpr int WTM = 64, WTN = 32;
    constexpr int FM = 4, FN = 2;

    const int ar0 = tid >> 4, ac = (tid & 15) * 8;
    const int ar1 = ar0 + 16;
    const int kt = K / BK;

    wmma::fragment<wmma::accumulator, 16, 16, 16, float> acc[FM][FN];
    #pragma unroll
    for (int i = 0; i < FM; i++)
        #pragma unroll
        for (int j = 0; j < FN; j++) wmma::fill_fragment(acc[i][j], 0.f);

    auto AsP = [&](int s) { return reinterpret_cast<__nv_bfloat16*>(dynsm + s * STAGE); };
    auto BsP = [&](int s) { return reinterpret_cast<__nv_bfloat16*>(dynsm + s * STAGE + ABYTES); };

    auto issue = [&](int s, int k0) {
        __nv_bfloat16* As = AsP(s);
        __nv_bfloat16* Bs = BsP(s);
        cp_async16((unsigned)__cvta_generic_to_shared(&As[ar0 * LDA + ac]),
                   &AT[(size_t)(k0 + ar0) * M + m0 + ac]);
        cp_async16((unsigned)__cvta_generic_to_shared(&As[ar1 * LDA + ac]),
                   &AT[(size_t)(k0 + ar1) * M + m0 + ac]);
        cp_async16((unsigned)__cvta_generic_to_shared(&Bs[ar0 * LDB + ac]),
                   &B[(size_t)(k0 + ar0) * N + n0 + ac]);
        cp_async16((unsigned)__cvta_generic_to_shared(&Bs[ar1 * LDB + ac]),
                   &B[(size_t)(k0 + ar1) * N + n0 + ac]);
    };

    issue(0, 0);         cp_commit();
    issue(1, BK);        cp_commit();

    for (int it = 0; it < kt; ++it) {
        cp_wait1();
        __syncthreads();
        int sb = it % 3;
        __nv_bfloat16* As = AsP(sb);
        __nv_bfloat16* Bs = BsP(sb);
        #pragma unroll
        for (int kk = 0; kk < BK; kk += 16) {
            wmma::fragment<wmma::matrix_a, 16, 16, 16, __nv_bfloat16, wmma::col_major> af[FM];
            wmma::fragment<wmma::matrix_b, 16, 16, 16, __nv_bfloat16, wmma::row_major> bf[FN];
            #pragma unroll
            for (int i = 0; i < FM; i++)
                wmma::load_matrix_sync(af[i], &As[kk * LDA + wm * WTM + i * 16], LDA);
            #pragma unroll
            for (int j = 0; j < FN; j++)
                wmma::load_matrix_sync(bf[j], &Bs[kk * LDB + wn * WTN + j * 16], LDB);
            #pragma unroll
            for (int i = 0; i < FM; i++)
                #pragma unroll
                for (int j = 0; j < FN; j++)
                    wmma::mma_sync(acc[i][j], af[i], bf[j], acc[i][j]);
        }
        if (it + 2 < kt) issue((it + 2) % 3, (it + 2) * BK);
        cp_commit();
    }
    #pragma unroll
    for (int i = 0; i < FM; i++)
        #pragma unroll
        for (int j = 0; j < FN; j++)
            wmma::store_matrix_sync(&C[(size_t)(m0 + wm * WTM + i * 16) * N + n0 + wn * WTN + j * 16],
                                    acc[i][j], N, wmma::mem_row_major);
}

// ---------------- out-proj wmma + fused transposed residual ----------------
__global__ __launch_bounds__(256) void mma_gemm_arow_res(const __nv_bfloat16* __restrict__ A,
                                                         const __nv_bfloat16* __restrict__ B,
                                                         float* __restrict__ out,
                                                         const float* __restrict__ x,
                                                         int M, int N, int K)
{
    constexpr int BM = 128, BN = 64, BK = 32;
    constexpr int LDA = BK + 8;
    constexpr int LDB = BN + 8;
    constexpr int LDC = BM + 4;
    constexpr int ASZ = BM * LDA * 2;
    constexpr int BSZ = BK * LDB * 2;
    constexpr int CSZ = BN * LDC * 4;
    constexpr int SMEM = (ASZ + BSZ) > CSZ ? (ASZ + BSZ) : CSZ;
    __shared__ __align__(16) unsigned char sraw[SMEM];
    __nv_bfloat16* As = reinterpret_cast<__nv_bfloat16*>(sraw);
    __nv_bfloat16* Bs = reinterpret_cast<__nv_bfloat16*>(sraw + ASZ);
    float* Cs = reinterpret_cast<float*>(sraw);

    const int tid = threadIdx.x;
    const int wid = tid >> 5;
    const int m0 = blockIdx.y * BM;
    const int n0 = blockIdx.x * BN;
    const int wm = wid & 3, wn = wid >> 2;
    constexpr int WTM = 32, WTN = 32;
    constexpr int FM = 2, FN = 2;

    const int ar0 = tid >> 2, aco = (tid & 3) * 8;
    const int ar1 = ar0 + 64;
    const int br = tid >> 3, bc = (tid & 7) * 8;

    wmma::fragment<wmma::accumulator, 16, 16, 16, float> acc[FM][FN];
    #pragma unroll
    for (int i = 0; i < FM; i++)
        #pragma unroll
        for (int j = 0; j < FN; j++) wmma::fill_fragment(acc[i][j], 0.f);

    uint4 pa0 = *reinterpret_cast<const uint4*>(&A[(size_t)(m0 + ar0) * K + aco]);
    uint4 pa1 = *reinterpret_cast<const uint4*>(&A[(size_t)(m0 + ar1) * K + aco]);
    uint4 pb  = *reinterpret_cast<const uint4*>(&B[(size_t)br * N + n0 + bc]);
    *reinterpret_cast<uint4*>(&As[ar0 * LDA + aco]) = pa0;
    *reinterpret_cast<uint4*>(&As[ar1 * LDA + aco]) = pa1;
    *reinterpret_cast<uint4*>(&Bs[br * LDB + bc])   = pb;
    __syncthreads();

    for (int k0 = 0; k0 < K; k0 += BK) {
        int kn = k0 + BK;
        if (kn < K) {
            pa0 = *reinterpret_cast<const uint4*>(&A[(size_t)(m0 + ar0) * K + kn + aco]);
            pa1 = *reinterpret_cast<const uint4*>(&A[(size_t)(m0 + ar1) * K + kn + aco]);
            pb  = *reinterpret_cast<const uint4*>(&B[(size_t)(kn + br) * N + n0 + bc]);
        }
        #pragma unroll
        for (int kk = 0; kk < BK; kk += 16) {
            wmma::fragment<wmma::matrix_a, 16, 16, 16, __nv_bfloat16, wmma::row_major> af[FM];
            wmma::fragment<wmma::matrix_b, 16, 16, 16, __nv_bfloat16, wmma::row_major> bf[FN];
            #pragma unroll
            for (int i = 0; i < FM; i++)
                wmma::load_matrix_sync(af[i], &As[(wm * WTM + i * 16) * LDA + kk], LDA);
            #pragma unroll
            for (int j = 0; j < FN; j++)
                wmma::load_matrix_sync(bf[j], &Bs[kk * LDB + wn * WTN + j * 16], LDB);
            #pragma unroll
            for (int i = 0; i < FM; i++)
                #pragma unroll
                for (int j = 0; j < FN; j++)
                    wmma::mma_sync(acc[i][j], af[i], bf[j], acc[i][j]);
        }
        __syncthreads();
        if (kn < K) {
            *reinterpret_cast<uint4*>(&As[ar0 * LDA + aco]) = pa0;
            *reinterpret_cast<uint4*>(&As[ar1 * LDA + aco]) = pa1;
            *reinterpret_cast<uint4*>(&Bs[br * LDB + bc])   = pb;
            __syncthreads();
        }
    }

    #pragma unroll
    for (int i = 0; i < FM; i++)
        #pragma unroll
        for (int j = 0; j < FN; j++)
            wmma::store_matrix_sync(&Cs[(wn * WTN + j * 16) * LDC + wm * WTM + i * 16],
                                    acc[i][j], LDC, wmma::mem_col_major);
    __syncthreads();

    int b   = m0 >> 10;
    int l0b = m0 & (LL - 1);
    #pragma unroll
    for (int idx = tid; idx < BM * BN; idx += 256) {
        int n = idx / BM;
        int m = idx % BM;
        size_t gi = ((size_t)(b * CC + n0 + n)) * LL + l0b + m;
        out[gi] = Cs[n * LDC + m] + x[gi];
    }
}

// ---------------- fused conv+SiLU+x-proj+dt: 8 tokens/block ----------------
// dynamic smem: sx[11*1024] | sc[8*1024] | ps[4*8*64] | sp[8*64]
__global__ __launch_bounds__(256) void convxproj_kernel(const float* __restrict__ xz,
                                                        const float* __restrict__ conv_w,
                                                        const float* __restrict__ conv_b,
                                                        const float* __restrict__ Wx,
                                                        const float* __restrict__ Wdt,
                                                        const float* __restrict__ bdt,
                                                        float* __restrict__ xc,
                                                        float* __restrict__ proj,
                                                        float* __restrict__ dt)
{
    extern __shared__ __align__(16) float dynf[];
    float* sx = dynf;                  // 11 x 1024
    float* sc = dynf + 11 * 1024;      // 8 x 1024
    float* ps = sc + 8 * 1024;         // 4 x 8 x 64
    float* sp = ps + 4 * 8 * 64;       // 8 x 64 (reduced proj)

    int tid = threadIdx.x;
    int t0 = blockIdx.x * 8;
    int l0 = t0 & (LL - 1);

    #pragma unroll
    for (int i = tid * 4; i < 11 * 1024; i += 256 * 4) {
        int row = i >> 10;
        int col = i & 1023;
        float4 v = make_float4(0.f, 0.f, 0.f, 0.f);
        if (l0 - 3 + row >= 0)
            v = *reinterpret_cast<const float4*>(&xz[(size_t)(t0 - 3 + row) * (2 * DI) + col]);
        *reinterpret_cast<float4*>(&sx[i]) = v;
    }
    __syncthreads();

    // conv + silu -> sc + global xc
    #pragma unroll
    for (int j = 0; j < 32; j++) {
        int o = j * 256 + tid;
        int tok = o >> 10, d = o & 1023;
        float v = conv_b[d];
        #pragma unroll
        for (int k = 0; k < 4; k++)
            v = fmaf(conv_w[d * 4 + k], sx[(tok + k) * 1024 + d], v);
        v *= 1.f / (1.f + __expf(-v));
        sc[tok * 1024 + d] = v;
        xc[(size_t)(t0 + tok) * DI + d] = v;
    }
    __syncthreads();

    // x-proj from sc
    int col = tid & 63, g = tid >> 6;
    int kbase = g * 256;
    float acc[8];
    #pragma unroll
    for (int i = 0; i < 8; i++) acc[i] = 0.f;
    #pragma unroll 4
    for (int k = 0; k < 256; k++) {
        float bv = __ldg(&Wx[(kbase + k) * 64 + col]);
        #pragma unroll
        for (int tok = 0; tok < 8; tok++)
            acc[tok] = fmaf(sc[tok * 1024 + kbase + k], bv, acc[tok]);
    }
    #pragma unroll
    for (int tok = 0; tok < 8; tok++) ps[(g * 8 + tok) * 64 + col] = acc[tok];
    __syncthreads();
    #pragma unroll
    for (int j2 = 0; j2 < 2; j2++) {
        int tok = (tid >> 6) + 4 * j2;
        float r = ps[(0 * 8 + tok) * 64 + col] + ps[(1 * 8 + tok) * 64 + col]
                + ps[(2 * 8 + tok) * 64 + col] + ps[(3 * 8 + tok) * 64 + col];
        sp[tok * 64 + col] = r;
        proj[(size_t)(t0 + tok) * 64 + col] = r;
    }
    __syncthreads();

    // dt = softplus(dtr @ Wdt + bdt): thread handles 4 d-cols x 8 tokens
    {
        int d0 = tid * 4;
        float da[8][4];
        #pragma unroll
        for (int tok = 0; tok < 8; tok++)
            #pragma unroll
            for (int j = 0; j < 4; j++) da[tok][j] = 0.f;
        #pragma unroll 8
        for (int k = 0; k < DTR; k++) {
            float4 w4 = *reinterpret_cast<const float4*>(&Wdt[k * DI + d0]);
            #pragma unroll
            for (int tok = 0; tok < 8; tok++) {
                float dv = sp[tok * 64 + k];
                da[tok][0] = fmaf(dv, w4.x, da[tok][0]);
                da[tok][1] = fmaf(dv, w4.y, da[tok][1]);
                da[tok][2] = fmaf(dv, w4.z, da[tok][2]);
                da[tok][3] = fmaf(dv, w4.w, da[tok][3]);
            }
        }
        float4 b4 = *reinterpret_cast<const float4*>(&bdt[d0]);
        #pragma unroll
        for (int tok = 0; tok < 8; tok++) {
            float4 o;
            o.x = da[tok][0] + b4.x; o.y = da[tok][1] + b4.y;
            o.z = da[tok][2] + b4.z; o.w = da[tok][3] + b4.w;
            o.x = (o.x > 20.f) ? o.x : log1pf(__expf(o.x));
            o.y = (o.y > 20.f) ? o.y : log1pf(__expf(o.y));
            o.z = (o.z > 20.f) ? o.z : log1pf(__expf(o.z));
            o.w = (o.w > 20.f) ? o.w : log1pf(__expf(o.w));
            *reinterpret_cast<float4*>(&dt[(size_t)(t0 + tok) * DI + d0]) = o;
        }
    }
}

// ---------------- chunked selective scan ----------------
__global__ __launch_bounds__(256) void scan_partial_kernel(const float* __restrict__ dt,
                                                           const float* __restrict__ xc,
                                                           const float* __restrict__ proj,
                                                           const float* __restrict__ A_log,
                                                           float* __restrict__ gP,
                                                           float* __restrict__ gH)
{
    int tid = threadIdx.x;
    int n = tid & 15;
    int G = blockIdx.x * 16 + (tid >> 4);
    int d = G & (DI - 1), b = (G >> 10) & 1, chunk = G >> 11;
    float a = -__expf(A_log[d * NS + n]);
    float P = 1.f, h = 0.f;
    int t0 = b * LL + chunk * CLEN;
    for (int l = 0; l < CLEN; l += 4) {
        float dtv[4], xcv[4], Bv[4];
        #pragma unroll
        for (int u = 0; u < 4; u++) {
            int t = t0 + l + u;
            dtv[u] = dt[(size_t)t * DI + d];
            xcv[u] = xc[(size_t)t * DI + d];
            Bv[u]  = proj[t * 64 + DTR + n];
        }
        #pragma unroll
        for (int u = 0; u < 4; u++) {
            float dA = __expf(dtv[u] * a);
            P *= dA;
            h = fmaf(dA, h, dtv[u] * xcv[u] * Bv[u]);
        }
    }
    gP[G * NS + n] = P;
    gH[G * NS + n] = h;
}

__global__ __launch_bounds__(256) void scan_combine_kernel(const float* __restrict__ gP,
                                                           const float* __restrict__ gH,
                                                           float* __restrict__ gh0)
{
    int id = blockIdx.x * 256 + threadIdx.x;
    int n = id & 15, d = (id >> 4) & (DI - 1), b = id >> 14;
    float h0 = 0.f;
    #pragma unroll
    for (int c = 0; c < NCH; c++) {
        int G = (c << 11) | (b << 10) | d;
        gh0[G * NS + n] = h0;
        h0 = fmaf(gP[G * NS + n], h0, gH[G * NS + n]);
    }
}

__global__ __launch_bounds__(256) void scan_final_kernel(const float* __restrict__ dt,
                                                         const float* __restrict__ xc,
                                                         const float* __restrict__ proj,
                                                         const float* __restrict__ xz,
                                                         const float* __restrict__ A_log,
                                                         const float* __restrict__ D_param,
                                                         const float* __restrict__ gh0,
                                                         __nv_bfloat16* __restrict__ y)
{
    int tid = threadIdx.x;
    int n = tid & 15;
    int G = blockIdx.x * 16 + (tid >> 4);
    int d = G & (DI - 1), b = (G >> 10) & 1, chunk = G >> 11;
    float a = -__expf(A_log[d * NS + n]);
    float Dp = D_param[d];
    float h = gh0[G * NS + n];
    int t0 = b * LL + chunk * CLEN;
    for (int l = 0; l < CLEN; l += 4) {
        float dtv[4], xcv[4], Bv[4], Cv[4], zv[4];
        #pragma unroll
        for (int u = 0; u < 4; u++) {
            int t = t0 + l + u;
            dtv[u] = dt[(size_t)t * DI + d];
            xcv[u] = xc[(size_t)t * DI + d];
            Bv[u]  = proj[t * 64 + DTR + n];
            Cv[u]  = proj[t * 64 + DTR + NS + n];
            zv[u]  = xz[(size_t)t * (2 * DI) + DI + d];
        }
        #pragma unroll
        for (int u = 0; u < 4; u++) {
            float dA = __expf(dtv[u] * a);
            h = fmaf(dA, h, dtv[u] * xcv[u] * Bv[u]);
            float p = h * Cv[u];
            p += __shfl_xor_sync(0xffffffffu, p, 8);
            p += __shfl_xor_sync(0xffffffffu, p, 4);
            p += __shfl_xor_sync(0xffffffffu, p, 2);
            p += __shfl_xor_sync(0xffffffffu, p, 1);
            if (n == 0) {
                int t = t0 + l + u;
                float sg = 1.f / (1.f + __expf(-zv[u]));
                y[(size_t)t * DI + d] =
                    __float2bfloat16((p + Dp * xcv[u]) * (zv[u] * sg));
            }
        }
    }
}

// ---------------- launch ----------------
extern "C" void kernel_launch(void* const* d_in, const int* in_sizes, int n_in,
                              void* d_out, int out_size)
{
    const float* x       = (const float*)d_in[0];
    const float* gamma   = (const float*)d_in[1];
    const float* beta    = (const float*)d_in[2];
    const float* W_in    = (const float*)d_in[3];
    const float* conv_w  = (const float*)d_in[4];
    const float* conv_b  = (const float*)d_in[5];
    const float* W_x     = (const float*)d_in[6];
    const float* W_dt    = (const float*)d_in[7];
    const float* b_dt    = (const float*)d_in[8];
    const float* A_log   = (const float*)d_in[9];
    const float* D_param = (const float*)d_in[10];
    const float* W_out   = (const float*)d_in[11];
    float* out = (float*)d_out;

    __nv_bfloat16 *p_xnT, *p_ybf, *p_Win, *p_Wout;
    float *p_xz, *p_xc, *p_proj, *p_dt, *p_P, *p_H, *p_h0;
    cudaGetSymbolAddress((void**)&p_xnT, g_xnT);
    cudaGetSymbolAddress((void**)&p_xz,  g_xz);
    cudaGetSymbolAddress((void**)&p_xc,  g_xc);
    cudaGetSymbolAddress((void**)&p_proj,g_proj);
    cudaGetSymbolAddress((void**)&p_dt,  g_dt);
    cudaGetSymbolAddress((void**)&p_ybf, g_ybf);
    cudaGetSymbolAddress((void**)&p_Win, g_Win_bf);
    cudaGetSymbolAddress((void**)&p_Wout,g_Wout_bf);
    cudaGetSymbolAddress((void**)&p_P,   g_P);
    cudaGetSymbolAddress((void**)&p_H,   g_H);
    cudaGetSymbolAddress((void**)&p_h0,  g_h0);

    constexpr int INPROJ_SMEM = 3 * (32 * 136 * 2) * 2;                         // 52224
    constexpr int CXP_SMEM    = (11 * 1024 + 8 * 1024 + 4 * 8 * 64 + 8 * 64) * 4; // 88064
    cudaFuncSetAttribute(mma_gemm_acol, cudaFuncAttributeMaxDynamicSharedMemorySize, INPROJ_SMEM);
    cudaFuncSetAttribute(convxproj_kernel, cudaFuncAttributeMaxDynamicSharedMemorySize, CXP_SMEM);

    f2bf_dual_kernel<<<(CC * 2 * DI + DI * CC) / 1024, 256>>>(W_in, p_Win, W_out, p_Wout);

    ln_kernel<<<BB * (LL / 32), 1024>>>(x, gamma, beta, p_xnT);

    {   // in-proj
        dim3 grid((2 * DI) / 128, NTOK / 128);
        mma_gemm_acol<<<grid, 256, INPROJ_SMEM>>>(p_xnT, p_Win, p_xz, NTOK, 2 * DI, CC);
    }

    // fused conv+silu+x-proj+dt
    convxproj_kernel<<<NTOK / 8, 256, CXP_SMEM>>>(p_xz, conv_w, conv_b, W_x, W_dt, b_dt,
                                                  p_xc, p_proj, p_dt);

    // chunked scan
    scan_partial_kernel<<<NCH * BB * DI / 16, 256>>>(p_dt, p_xc, p_proj, A_log, p_P, p_H);
    scan_combine_kernel<<<BB * DI * NS / 256, 256>>>(p_P, p_H, p_h0);
    scan_final_kernel<<<NCH * BB * DI / 16, 256>>>(p_dt, p_xc, p_proj, p_xz,
                                                   A_log, D_param, p_h0, p_ybf);

    {   // out-proj + residual
        dim3 grid(CC / 64, NTOK / 128);
        mma_gemm_arow_res<<<grid, 256>>>(p_ybf, p_Wout, out, x, NTOK, CC, DI);
    }
}